// round 1
// baseline (speedup 1.0000x reference)
#include <cuda_runtime.h>

// Problem constants
#define HEADS   8
#define DK      64
#define DV      192
#define BATCH   4
#define SEQ     1536
#define DMODEL  1536
#define MROWS   (BATCH*SEQ)          // 6144
#define NQK     (HEADS*DK)           // 512
#define NV      (HEADS*DV)           // 1536

// Scratch: projected Q, K, V (device globals — allocation-free per harness rules)
__device__ float g_Q[MROWS * NQK];   // 6144 x 512   (12.6 MB)  (pre-scaled by dk^-0.5)
__device__ float g_K[MROWS * NQK];   // 6144 x 512
__device__ float g_V[MROWS * NV];    // 6144 x 1536  (37.7 MB)

// ---------------------------------------------------------------------------
// SGEMM: C[M,N] = alpha * A[M,K] @ B[K,N], all row-major.
// BM=BN=128, BK=16, 256 threads, 8x8 per-thread microtile.
// grid = (N/128, M/128)
// ---------------------------------------------------------------------------
__global__ __launch_bounds__(256)
void sgemm128(const float* __restrict__ A, const float* __restrict__ Bw,
              float* __restrict__ C, int N, int K, float alpha)
{
    __shared__ float As[16][132];   // transposed A tile, padded
    __shared__ float Bs[16][128];

    const int tid = threadIdx.x;
    const int bm = blockIdx.y, bn = blockIdx.x;
    const int tm = tid >> 4, tn = tid & 15;

    float acc[8][8];
#pragma unroll
    for (int i = 0; i < 8; i++)
#pragma unroll
        for (int j = 0; j < 8; j++) acc[i][j] = 0.f;

    const float* Ab = A + (size_t)bm * 128 * K;
    const float* Bb = Bw + bn * 128;

    for (int k0 = 0; k0 < K; k0 += 16) {
        // load A tile (128x16), store transposed
#pragma unroll
        for (int r = 0; r < 2; r++) {
            int t = tid + r * 256;
            int ar = t >> 2, ac = (t & 3) << 2;
            float4 v = *(const float4*)(Ab + (size_t)ar * K + k0 + ac);
            As[ac + 0][ar] = v.x; As[ac + 1][ar] = v.y;
            As[ac + 2][ar] = v.z; As[ac + 3][ar] = v.w;
        }
        // load B tile (16x128)
#pragma unroll
        for (int r = 0; r < 2; r++) {
            int t = tid + r * 256;
            int br = t >> 5, bc = (t & 31) << 2;
            *(float4*)(&Bs[br][bc]) = *(const float4*)(Bb + (size_t)(k0 + br) * N + bc);
        }
        __syncthreads();

#pragma unroll
        for (int k = 0; k < 16; k++) {
            float a[8], b[8];
            *(float4*)(a)     = *(float4*)(&As[k][tm * 8]);
            *(float4*)(a + 4) = *(float4*)(&As[k][tm * 8 + 4]);
            *(float4*)(b)     = *(float4*)(&Bs[k][tn * 8]);
            *(float4*)(b + 4) = *(float4*)(&Bs[k][tn * 8 + 4]);
#pragma unroll
            for (int i = 0; i < 8; i++)
#pragma unroll
                for (int j = 0; j < 8; j++)
                    acc[i][j] += a[i] * b[j];
        }
        __syncthreads();
    }

#pragma unroll
    for (int i = 0; i < 8; i++) {
        int row = bm * 128 + tm * 8 + i;
        float* Cr = C + (size_t)row * N + bn * 128 + tn * 8;
        float4 v0 = make_float4(acc[i][0] * alpha, acc[i][1] * alpha,
                                acc[i][2] * alpha, acc[i][3] * alpha);
        float4 v1 = make_float4(acc[i][4] * alpha, acc[i][5] * alpha,
                                acc[i][6] * alpha, acc[i][7] * alpha);
        *(float4*)(Cr)     = v0;
        *(float4*)(Cr + 4) = v1;
    }
}

// ---------------------------------------------------------------------------
// Flash attention (fp32, online softmax).
// grid = (SEQ/64, BATCH*HEADS), 256 threads.
// Q tile 64x64 (Q already scaled), KV tile 64; O tile 64x192 in registers.
// Thread layout: ty=tid/16 owns rows ty*4..+3; tx=tid%16.
//   S-compute cols: tx*4..+3 ; O cols: 3 chunks of 64, col = chunk*64 + tx*4.
// K tile stored with quad-XOR swizzle for conflict-free LDS.128.
// Dynamic smem: Qs 64x68 | Ks 64x64 | Ps 64x68 | Vs 64x196  = 25344 floats.
// ---------------------------------------------------------------------------
#define FLASH_SMEM_FLOATS 25344

__global__ __launch_bounds__(256)
void flash_kernel(const float* __restrict__ Q, const float* __restrict__ Kp,
                  const float* __restrict__ V, float* __restrict__ out)
{
    extern __shared__ float sm[];
    float* Qs = sm;            // 64*68  = 4352
    float* Ks = sm + 4352;     // 64*64  = 4096 (swizzled)
    float* Ps = sm + 8448;     // 64*68  = 4352
    float* Vs = sm + 12800;    // 64*196 = 12544

    const int tid = threadIdx.x;
    const int ty = tid >> 4, tx = tid & 15;
    const int qt = blockIdx.x, bh = blockIdx.y;
    const int b = bh >> 3, h = bh & 7;
    const int q0 = qt * 64;
    const int i0 = ty * 4;

    // Load Q tile (64 rows x 16 quads)
    for (int t = tid; t < 64 * 16; t += 256) {
        int r = t >> 4, kq = t & 15;
        float4 v = *(const float4*)(Q + (size_t)(b * SEQ + q0 + r) * NQK + h * DK + kq * 4);
        *(float4*)(Qs + r * 68 + kq * 4) = v;
    }

    float m_i[4], l_i[4];
    float o[4][3][4];
#pragma unroll
    for (int ii = 0; ii < 4; ii++) {
        m_i[ii] = -1e30f; l_i[ii] = 0.f;
#pragma unroll
        for (int c = 0; c < 3; c++)
#pragma unroll
            for (int cc = 0; cc < 4; cc++) o[ii][c][cc] = 0.f;
    }

    for (int kt = 0; kt < SEQ / 64; kt++) {
        const int kv0 = kt * 64;
        __syncthreads();   // prev-iter consumers done; also fences Qs on iter 0

        // Load K tile, swizzled: quad' = kq ^ ((row/4)&7)
        for (int t = tid; t < 64 * 16; t += 256) {
            int r = t >> 4, kq = t & 15;
            float4 v = *(const float4*)(Kp + (size_t)(b * SEQ + kv0 + r) * NQK + h * DK + kq * 4);
            *(float4*)(Ks + r * 64 + ((kq ^ ((r >> 2) & 7)) << 2)) = v;
        }
        // Load V tile (64 rows x 48 quads)
        for (int t = tid; t < 64 * 48; t += 256) {
            int r = t / 48, cq = t % 48;
            float4 v = *(const float4*)(V + (size_t)(b * SEQ + kv0 + r) * NV + h * DV + cq * 4);
            *(float4*)(Vs + r * 196 + cq * 4) = v;
        }
        __syncthreads();

        // S = Q @ K^T  (per-thread 4x4)
        float s[4][4];
#pragma unroll
        for (int ii = 0; ii < 4; ii++)
#pragma unroll
            for (int jj = 0; jj < 4; jj++) s[ii][jj] = 0.f;

#pragma unroll
        for (int kq = 0; kq < 16; kq++) {
            float4 q4[4];
#pragma unroll
            for (int ii = 0; ii < 4; ii++)
                q4[ii] = *(float4*)(Qs + (i0 + ii) * 68 + kq * 4);
#pragma unroll
            for (int jj = 0; jj < 4; jj++) {
                int j = tx * 4 + jj;
                float4 k4 = *(float4*)(Ks + j * 64 + ((kq ^ (tx & 7)) << 2));
#pragma unroll
                for (int ii = 0; ii < 4; ii++)
                    s[ii][jj] += q4[ii].x * k4.x + q4[ii].y * k4.y
                               + q4[ii].z * k4.z + q4[ii].w * k4.w;
            }
        }

        // Online softmax per row (16 lanes of a half-warp share a row group)
#pragma unroll
        for (int ii = 0; ii < 4; ii++) {
            float mx = fmaxf(fmaxf(s[ii][0], s[ii][1]), fmaxf(s[ii][2], s[ii][3]));
#pragma unroll
            for (int off = 8; off >= 1; off >>= 1)
                mx = fmaxf(mx, __shfl_xor_sync(0xffffffffu, mx, off));
            float m_new = fmaxf(m_i[ii], mx);
            float alpha = __expf(m_i[ii] - m_new);
            float rs = 0.f;
#pragma unroll
            for (int jj = 0; jj < 4; jj++) {
                s[ii][jj] = __expf(s[ii][jj] - m_new);
                rs += s[ii][jj];
            }
#pragma unroll
            for (int off = 8; off >= 1; off >>= 1)
                rs += __shfl_xor_sync(0xffffffffu, rs, off);
            l_i[ii] = l_i[ii] * alpha + rs;
            m_i[ii] = m_new;
#pragma unroll
            for (int c = 0; c < 3; c++)
#pragma unroll
                for (int cc = 0; cc < 4; cc++) o[ii][c][cc] *= alpha;
            *(float4*)(Ps + (i0 + ii) * 68 + tx * 4) = *(float4*)(&s[ii][0]);
        }
        __syncthreads();

        // O += P @ V
#pragma unroll 4
        for (int kk4 = 0; kk4 < 16; kk4++) {
            float4 p4[4];
#pragma unroll
            for (int ii = 0; ii < 4; ii++)
                p4[ii] = *(float4*)(Ps + (i0 + ii) * 68 + kk4 * 4);
#pragma unroll
            for (int qq = 0; qq < 4; qq++) {
                int kk = kk4 * 4 + qq;
                float4 v4[3];
#pragma unroll
                for (int c = 0; c < 3; c++)
                    v4[c] = *(float4*)(Vs + kk * 196 + c * 64 + tx * 4);
#pragma unroll
                for (int ii = 0; ii < 4; ii++) {
                    float p = (qq == 0) ? p4[ii].x : (qq == 1) ? p4[ii].y
                             : (qq == 2) ? p4[ii].z : p4[ii].w;
#pragma unroll
                    for (int c = 0; c < 3; c++) {
                        o[ii][c][0] += p * v4[c].x;
                        o[ii][c][1] += p * v4[c].y;
                        o[ii][c][2] += p * v4[c].z;
                        o[ii][c][3] += p * v4[c].w;
                    }
                }
            }
        }
    }

    // Epilogue: normalize and write out[b, s, h*DV + c]
#pragma unroll
    for (int ii = 0; ii < 4; ii++) {
        float inv = 1.0f / l_i[ii];
        int row = b * SEQ + q0 + i0 + ii;
        float* outp = out + (size_t)row * NV + h * DV;
#pragma unroll
        for (int c = 0; c < 3; c++) {
            float4 v = make_float4(o[ii][c][0] * inv, o[ii][c][1] * inv,
                                   o[ii][c][2] * inv, o[ii][c][3] * inv);
            *(float4*)(outp + c * 64 + tx * 4) = v;
        }
    }
}

// ---------------------------------------------------------------------------
extern "C" void kernel_launch(void* const* d_in, const int* in_sizes, int n_in,
                              void* d_out, int out_size)
{
    const float* X  = (const float*)d_in[0];
    const float* Wq = (const float*)d_in[1];
    const float* Wk = (const float*)d_in[2];
    const float* Wv = (const float*)d_in[3];
    float* out = (float*)d_out;

    void *pq, *pk, *pv;
    cudaGetSymbolAddress(&pq, g_Q);
    cudaGetSymbolAddress(&pk, g_K);
    cudaGetSymbolAddress(&pv, g_V);

    // Projections (scale dk^-0.5 folded into Q)
    dim3 gqk(NQK / 128, MROWS / 128);      // (4, 48)
    sgemm128<<<gqk, 256>>>(X, Wq, (float*)pq, NQK, DMODEL, 0.125f);
    sgemm128<<<gqk, 256>>>(X, Wk, (float*)pk, NQK, DMODEL, 1.0f);
    dim3 gv(NV / 128, MROWS / 128);        // (12, 48)
    sgemm128<<<gv, 256>>>(X, Wv, (float*)pv, NV, DMODEL, 1.0f);

    // Flash attention
    int smem_bytes = FLASH_SMEM_FLOATS * 4;   // 101376 B
    cudaFuncSetAttribute(flash_kernel,
                         cudaFuncAttributeMaxDynamicSharedMemorySize, smem_bytes);
    flash_kernel<<<dim3(SEQ / 64, BATCH * HEADS), 256, smem_bytes>>>(
        (const float*)pq, (const float*)pk, (const float*)pv, out);
}

// round 2
// speedup vs baseline: 1.5844x; 1.5844x over previous
#include <cuda_runtime.h>

#define HEADS   8
#define DK      64
#define DV      192
#define BATCH   4
#define SEQ     1536
#define DMODEL  1536
#define MROWS   (BATCH*SEQ)          // 6144
#define NQK     (HEADS*DK)           // 512
#define NV      (HEADS*DV)           // 1536

// Scratch (allocation-free per harness rules)
__device__ float g_Q[MROWS * NQK];
__device__ float g_K[MROWS * NQK];
__device__ float g_V[MROWS * NV];

// ---------------------------------------------------------------------------
// tf32 helpers
// ---------------------------------------------------------------------------
__device__ __forceinline__ unsigned f2tf(float x) {
    unsigned u; asm("cvt.rna.tf32.f32 %0, %1;" : "=r"(u) : "f"(x)); return u;
}
__device__ __forceinline__ void split_tf(float x, float& hi, float& lo) {
    hi = __uint_as_float(f2tf(x));
    lo = __uint_as_float(f2tf(x - hi));
}
__device__ __forceinline__ void mma_tf32(float* d, const unsigned* a, const unsigned* b) {
    asm volatile(
        "mma.sync.aligned.m16n8k8.row.col.f32.tf32.tf32.f32 "
        "{%0,%1,%2,%3}, {%4,%5,%6,%7}, {%8,%9}, {%0,%1,%2,%3};\n"
        : "+f"(d[0]), "+f"(d[1]), "+f"(d[2]), "+f"(d[3])
        : "r"(a[0]), "r"(a[1]), "r"(a[2]), "r"(a[3]), "r"(b[0]), "r"(b[1]));
}

// ---------------------------------------------------------------------------
// 3x-tf32 GEMM: C[M,N] = alpha * A[M,K] @ B[K,N], row-major.
// BM=128 BN=128 BK=32, 256 threads (8 warps, 4x2), warp tile 32x64.
// Smem: Ah/Al [128][36] (m,k) ; Bh/Bl [32][136] (k,n). Frag LDS conflict-free.
// ---------------------------------------------------------------------------
#define GEMM_SMEM_BYTES ((2*128*36 + 2*32*136) * 4)   // 71680

__global__ __launch_bounds__(256)
void gemm_tf32x3(const float* __restrict__ A, const float* __restrict__ Bw,
                 float* __restrict__ C, int N, int K, float alpha)
{
    extern __shared__ float sg[];
    float* Ah = sg;                  // 128*36 = 4608
    float* Al = sg + 4608;
    float* Bh = sg + 9216;           // 32*136 = 4352
    float* Bl = sg + 13568;

    const int tid  = threadIdx.x;
    const int lane = tid & 31, wid = tid >> 5;
    const int g = lane >> 2, tg = lane & 3;
    const int wm = (wid >> 1) * 32, wn = (wid & 1) * 64;
    const int bm = blockIdx.y, bn = blockIdx.x;

    float d[2][8][4];
#pragma unroll
    for (int mt = 0; mt < 2; mt++)
#pragma unroll
        for (int nt = 0; nt < 8; nt++)
#pragma unroll
            for (int i = 0; i < 4; i++) d[mt][nt][i] = 0.f;

    for (int k0 = 0; k0 < K; k0 += 32) {
        // A tile 128x32
#pragma unroll
        for (int r = 0; r < 4; r++) {
            int idx = tid + r * 256;
            int ar = idx >> 3, ac = (idx & 7) << 2;
            float4 v = *(const float4*)(A + (size_t)(bm * 128 + ar) * K + k0 + ac);
            float h0,l0,h1,l1,h2,l2,h3,l3;
            split_tf(v.x,h0,l0); split_tf(v.y,h1,l1);
            split_tf(v.z,h2,l2); split_tf(v.w,h3,l3);
            *(float4*)(Ah + ar * 36 + ac) = make_float4(h0,h1,h2,h3);
            *(float4*)(Al + ar * 36 + ac) = make_float4(l0,l1,l2,l3);
        }
        // B tile 32x128
#pragma unroll
        for (int r = 0; r < 4; r++) {
            int idx = tid + r * 256;
            int br = idx >> 5, bc = (idx & 31) << 2;
            float4 v = *(const float4*)(Bw + (size_t)(k0 + br) * N + bn * 128 + bc);
            float h0,l0,h1,l1,h2,l2,h3,l3;
            split_tf(v.x,h0,l0); split_tf(v.y,h1,l1);
            split_tf(v.z,h2,l2); split_tf(v.w,h3,l3);
            *(float4*)(Bh + br * 136 + bc) = make_float4(h0,h1,h2,h3);
            *(float4*)(Bl + br * 136 + bc) = make_float4(l0,l1,l2,l3);
        }
        __syncthreads();

#pragma unroll
        for (int ks = 0; ks < 4; ks++) {
            int kk = ks * 8;
            unsigned ah[2][4], al[2][4];
#pragma unroll
            for (int mt = 0; mt < 2; mt++) {
                int r0 = wm + mt * 16 + g;
                ah[mt][0] = __float_as_uint(Ah[r0 * 36 + kk + tg]);
                ah[mt][1] = __float_as_uint(Ah[(r0 + 8) * 36 + kk + tg]);
                ah[mt][2] = __float_as_uint(Ah[r0 * 36 + kk + tg + 4]);
                ah[mt][3] = __float_as_uint(Ah[(r0 + 8) * 36 + kk + tg + 4]);
                al[mt][0] = __float_as_uint(Al[r0 * 36 + kk + tg]);
                al[mt][1] = __float_as_uint(Al[(r0 + 8) * 36 + kk + tg]);
                al[mt][2] = __float_as_uint(Al[r0 * 36 + kk + tg + 4]);
                al[mt][3] = __float_as_uint(Al[(r0 + 8) * 36 + kk + tg + 4]);
            }
            unsigned bh[8][2], bl[8][2];
#pragma unroll
            for (int nt = 0; nt < 8; nt++) {
                int c = wn + nt * 8 + g;
                bh[nt][0] = __float_as_uint(Bh[(kk + tg) * 136 + c]);
                bh[nt][1] = __float_as_uint(Bh[(kk + tg + 4) * 136 + c]);
                bl[nt][0] = __float_as_uint(Bl[(kk + tg) * 136 + c]);
                bl[nt][1] = __float_as_uint(Bl[(kk + tg + 4) * 136 + c]);
            }
#pragma unroll
            for (int mt = 0; mt < 2; mt++)
#pragma unroll
                for (int nt = 0; nt < 8; nt++) {
                    mma_tf32(d[mt][nt], ah[mt], bh[nt]);
                    mma_tf32(d[mt][nt], ah[mt], bl[nt]);
                    mma_tf32(d[mt][nt], al[mt], bh[nt]);
                }
        }
        __syncthreads();
    }

    // Epilogue
#pragma unroll
    for (int mt = 0; mt < 2; mt++) {
        int r0 = bm * 128 + wm + mt * 16 + g;
#pragma unroll
        for (int nt = 0; nt < 8; nt++) {
            int c = bn * 128 + wn + nt * 8 + 2 * tg;
            *(float2*)(C + (size_t)r0 * N + c) =
                make_float2(d[mt][nt][0] * alpha, d[mt][nt][1] * alpha);
            *(float2*)(C + (size_t)(r0 + 8) * N + c) =
                make_float2(d[mt][nt][2] * alpha, d[mt][nt][3] * alpha);
        }
    }
}

// ---------------------------------------------------------------------------
// Flash attention, tensor-core:
//   Q tile 128 (8 warps x m16), KV tile 64.
//   S = QK^T in 3x-tf32 (fp32-accurate). P@V in 1x-tf32.
// Smem floats: Qh/Ql 128x68, Kh/Kl 64x68, Ps 128x68, Vs 64x200 => 190464 B.
// ---------------------------------------------------------------------------
#define FLASH_SMEM_BYTES ((3*128*68 + 2*64*68 + 64*200) * 4)   // 190464

__global__ __launch_bounds__(256, 1)
void flash_tc(const float* __restrict__ Q, const float* __restrict__ Kp,
              const float* __restrict__ V, float* __restrict__ out)
{
    extern __shared__ float sf[];
    float* Qh = sf;              // 128*68 = 8704
    float* Ql = sf + 8704;
    float* Kh = sf + 17408;      // 64*68 = 4352
    float* Kl = sf + 21760;
    float* Ps = sf + 26112;      // 128*68
    float* Vs = sf + 34816;      // 64*200 = 12800

    const int tid  = threadIdx.x;
    const int lane = tid & 31, wid = tid >> 5;
    const int g = lane >> 2, tg = lane & 3;
    const int w16 = wid * 16;
    const int b = blockIdx.y >> 3, h = blockIdx.y & 7;
    const int q0 = blockIdx.x * 128;

    // Load Q tile 128x64 (hi/lo split)
#pragma unroll
    for (int r = 0; r < 8; r++) {
        int idx = tid + r * 256;
        int qr = idx >> 4, qc = (idx & 15) << 2;
        float4 v = *(const float4*)(Q + (size_t)(b * SEQ + q0 + qr) * NQK + h * DK + qc);
        float h0,l0,h1,l1,h2,l2,h3,l3;
        split_tf(v.x,h0,l0); split_tf(v.y,h1,l1);
        split_tf(v.z,h2,l2); split_tf(v.w,h3,l3);
        *(float4*)(Qh + qr * 68 + qc) = make_float4(h0,h1,h2,h3);
        *(float4*)(Ql + qr * 68 + qc) = make_float4(l0,l1,l2,l3);
    }

    float m0 = -1e30f, m1 = -1e30f, l0s = 0.f, l1s = 0.f;
    float o[24][4];
#pragma unroll
    for (int nt = 0; nt < 24; nt++)
#pragma unroll
        for (int i = 0; i < 4; i++) o[nt][i] = 0.f;

    for (int kt = 0; kt < SEQ / 64; kt++) {
        const int kv0 = kt * 64;
        __syncthreads();

        // K tile 64x64 (hi/lo)
#pragma unroll
        for (int r = 0; r < 4; r++) {
            int idx = tid + r * 256;
            int kr = idx >> 4, kc = (idx & 15) << 2;
            float4 v = *(const float4*)(Kp + (size_t)(b * SEQ + kv0 + kr) * NQK + h * DK + kc);
            float h0,l0,h1,l1,h2,l2,h3,l3;
            split_tf(v.x,h0,l0); split_tf(v.y,h1,l1);
            split_tf(v.z,h2,l2); split_tf(v.w,h3,l3);
            *(float4*)(Kh + kr * 68 + kc) = make_float4(h0,h1,h2,h3);
            *(float4*)(Kl + kr * 68 + kc) = make_float4(l0,l1,l2,l3);
        }
        // V tile 64x192 (single tf32)
#pragma unroll
        for (int r = 0; r < 12; r++) {
            int idx = tid + r * 256;
            int vr = idx / 48, vq = idx % 48;
            float4 v = *(const float4*)(V + (size_t)(b * SEQ + kv0 + vr) * NV + h * DV + vq * 4);
            v.x = __uint_as_float(f2tf(v.x)); v.y = __uint_as_float(f2tf(v.y));
            v.z = __uint_as_float(f2tf(v.z)); v.w = __uint_as_float(f2tf(v.w));
            *(float4*)(Vs + vr * 200 + vq * 4) = v;
        }
        __syncthreads();

        // ---- S = Q @ K^T (3x tf32) ----
        float s[8][4];
#pragma unroll
        for (int nt = 0; nt < 8; nt++)
#pragma unroll
            for (int i = 0; i < 4; i++) s[nt][i] = 0.f;

#pragma unroll
        for (int ks = 0; ks < 8; ks++) {
            int kk = ks * 8;
            unsigned qh[4], ql[4];
            qh[0] = __float_as_uint(Qh[(w16 + g) * 68 + kk + tg]);
            qh[1] = __float_as_uint(Qh[(w16 + g + 8) * 68 + kk + tg]);
            qh[2] = __float_as_uint(Qh[(w16 + g) * 68 + kk + tg + 4]);
            qh[3] = __float_as_uint(Qh[(w16 + g + 8) * 68 + kk + tg + 4]);
            ql[0] = __float_as_uint(Ql[(w16 + g) * 68 + kk + tg]);
            ql[1] = __float_as_uint(Ql[(w16 + g + 8) * 68 + kk + tg]);
            ql[2] = __float_as_uint(Ql[(w16 + g) * 68 + kk + tg + 4]);
            ql[3] = __float_as_uint(Ql[(w16 + g + 8) * 68 + kk + tg + 4]);
#pragma unroll
            for (int nt = 0; nt < 8; nt++) {
                unsigned kh[2], kl[2];
                kh[0] = __float_as_uint(Kh[(nt * 8 + g) * 68 + kk + tg]);
                kh[1] = __float_as_uint(Kh[(nt * 8 + g) * 68 + kk + tg + 4]);
                kl[0] = __float_as_uint(Kl[(nt * 8 + g) * 68 + kk + tg]);
                kl[1] = __float_as_uint(Kl[(nt * 8 + g) * 68 + kk + tg + 4]);
                mma_tf32(s[nt], qh, kh);
                mma_tf32(s[nt], qh, kl);
                mma_tf32(s[nt], ql, kh);
            }
        }

        // ---- online softmax (rows g and g+8 of this warp's 16-row band) ----
        float mx0 = -1e30f, mx1 = -1e30f;
#pragma unroll
        for (int nt = 0; nt < 8; nt++) {
            mx0 = fmaxf(mx0, fmaxf(s[nt][0], s[nt][1]));
            mx1 = fmaxf(mx1, fmaxf(s[nt][2], s[nt][3]));
        }
        mx0 = fmaxf(mx0, __shfl_xor_sync(0xffffffffu, mx0, 1));
        mx0 = fmaxf(mx0, __shfl_xor_sync(0xffffffffu, mx0, 2));
        mx1 = fmaxf(mx1, __shfl_xor_sync(0xffffffffu, mx1, 1));
        mx1 = fmaxf(mx1, __shfl_xor_sync(0xffffffffu, mx1, 2));

        float nm0 = fmaxf(m0, mx0), nm1 = fmaxf(m1, mx1);
        float a0 = __expf(m0 - nm0), a1 = __expf(m1 - nm1);
        float sum0 = 0.f, sum1 = 0.f;
#pragma unroll
        for (int nt = 0; nt < 8; nt++) {
            s[nt][0] = __expf(s[nt][0] - nm0); sum0 += s[nt][0];
            s[nt][1] = __expf(s[nt][1] - nm0); sum0 += s[nt][1];
            s[nt][2] = __expf(s[nt][2] - nm1); sum1 += s[nt][2];
            s[nt][3] = __expf(s[nt][3] - nm1); sum1 += s[nt][3];
        }
        sum0 += __shfl_xor_sync(0xffffffffu, sum0, 1);
        sum0 += __shfl_xor_sync(0xffffffffu, sum0, 2);
        sum1 += __shfl_xor_sync(0xffffffffu, sum1, 1);
        sum1 += __shfl_xor_sync(0xffffffffu, sum1, 2);
        l0s = l0s * a0 + sum0;  l1s = l1s * a1 + sum1;
        m0 = nm0;  m1 = nm1;

#pragma unroll
        for (int nt = 0; nt < 24; nt++) {
            o[nt][0] *= a0; o[nt][1] *= a0;
            o[nt][2] *= a1; o[nt][3] *= a1;
        }
        // store P (tf32-rounded)
#pragma unroll
        for (int nt = 0; nt < 8; nt++) {
            *(float2*)(Ps + (w16 + g) * 68 + nt * 8 + 2 * tg) =
                make_float2(__uint_as_float(f2tf(s[nt][0])), __uint_as_float(f2tf(s[nt][1])));
            *(float2*)(Ps + (w16 + g + 8) * 68 + nt * 8 + 2 * tg) =
                make_float2(__uint_as_float(f2tf(s[nt][2])), __uint_as_float(f2tf(s[nt][3])));
        }
        __syncwarp();

        // ---- O += P @ V (1x tf32) ----
#pragma unroll
        for (int ks = 0; ks < 8; ks++) {
            int kk = ks * 8;
            unsigned ap[4];
            ap[0] = __float_as_uint(Ps[(w16 + g) * 68 + kk + tg]);
            ap[1] = __float_as_uint(Ps[(w16 + g + 8) * 68 + kk + tg]);
            ap[2] = __float_as_uint(Ps[(w16 + g) * 68 + kk + tg + 4]);
            ap[3] = __float_as_uint(Ps[(w16 + g + 8) * 68 + kk + tg + 4]);
#pragma unroll
            for (int nt = 0; nt < 24; nt++) {
                unsigned bv[2];
                bv[0] = __float_as_uint(Vs[(kk + tg) * 200 + nt * 8 + g]);
                bv[1] = __float_as_uint(Vs[(kk + tg + 4) * 200 + nt * 8 + g]);
                mma_tf32(o[nt], ap, bv);
            }
        }
    }

    // Epilogue
    float i0 = 1.f / l0s, i1 = 1.f / l1s;
    int r0 = b * SEQ + q0 + w16 + g, r1 = r0 + 8;
#pragma unroll
    for (int nt = 0; nt < 24; nt++) {
        int c = h * DV + nt * 8 + 2 * tg;
        *(float2*)(out + (size_t)r0 * NV + c) = make_float2(o[nt][0] * i0, o[nt][1] * i0);
        *(float2*)(out + (size_t)r1 * NV + c) = make_float2(o[nt][2] * i1, o[nt][3] * i1);
    }
}

// ---------------------------------------------------------------------------
extern "C" void kernel_launch(void* const* d_in, const int* in_sizes, int n_in,
                              void* d_out, int out_size)
{
    const float* X  = (const float*)d_in[0];
    const float* Wq = (const float*)d_in[1];
    const float* Wk = (const float*)d_in[2];
    const float* Wv = (const float*)d_in[3];
    float* out = (float*)d_out;

    void *pq, *pk, *pv;
    cudaGetSymbolAddress(&pq, g_Q);
    cudaGetSymbolAddress(&pk, g_K);
    cudaGetSymbolAddress(&pv, g_V);

    static bool attr_set = false;
    if (!attr_set) {
        cudaFuncSetAttribute(gemm_tf32x3,
            cudaFuncAttributeMaxDynamicSharedMemorySize, GEMM_SMEM_BYTES);
        cudaFuncSetAttribute(flash_tc,
            cudaFuncAttributeMaxDynamicSharedMemorySize, FLASH_SMEM_BYTES);
        attr_set = true;
    }

    dim3 gqk(NQK / 128, MROWS / 128);   // (4, 48)
    gemm_tf32x3<<<gqk, 256, GEMM_SMEM_BYTES>>>(X, Wq, (float*)pq, NQK, DMODEL, 0.125f);
    gemm_tf32x3<<<gqk, 256, GEMM_SMEM_BYTES>>>(X, Wk, (float*)pk, NQK, DMODEL, 1.0f);
    dim3 gv(NV / 128, MROWS / 128);     // (12, 48)
    gemm_tf32x3<<<gv, 256, GEMM_SMEM_BYTES>>>(X, Wv, (float*)pv, NV, DMODEL, 1.0f);

    flash_tc<<<dim3(SEQ / 128, BATCH * HEADS), 256, FLASH_SMEM_BYTES>>>(
        (const float*)pq, (const float*)pk, (const float*)pv, out);
}

// round 3
// speedup vs baseline: 2.8755x; 1.8149x over previous
#include <cuda_runtime.h>
#include <cuda_bf16.h>

#define HEADS   8
#define DK      64
#define DV      192
#define BATCH   4
#define SEQ     1536
#define DMODEL  1536
#define MROWS   (BATCH*SEQ)          // 6144
#define NQK     (HEADS*DK)           // 512
#define NV      (HEADS*DV)           // 1536

// ------------------------- global scratch (no allocs) -----------------------
__device__ __nv_bfloat16 g_Xh[MROWS * DMODEL];
__device__ __nv_bfloat16 g_Xl[MROWS * DMODEL];
__device__ __nv_bfloat16 g_Wqh[DMODEL * NQK],  g_Wql[DMODEL * NQK];
__device__ __nv_bfloat16 g_Wkh[DMODEL * NQK],  g_Wkl[DMODEL * NQK];
__device__ __nv_bfloat16 g_Wvh[DMODEL * NV],   g_Wvl[DMODEL * NV];
__device__ __nv_bfloat16 g_Qh[MROWS * NQK],    g_Ql[MROWS * NQK];
__device__ __nv_bfloat16 g_Kh[MROWS * NQK],    g_Kl[MROWS * NQK];
__device__ float         g_V [MROWS * NV];

// ------------------------------- helpers ------------------------------------
__device__ __forceinline__ unsigned s2u(const void* p) {
    return (unsigned)__cvta_generic_to_shared(p);
}
__device__ __forceinline__ unsigned f2tf(float x) {
    unsigned u; asm("cvt.rna.tf32.f32 %0, %1;" : "=r"(u) : "f"(x)); return u;
}
__device__ __forceinline__ unsigned pack_bf2(__nv_bfloat16 a, __nv_bfloat16 b) {
    return (unsigned)__bfloat16_as_ushort(a) | ((unsigned)__bfloat16_as_ushort(b) << 16);
}
// split two floats into packed-hi and packed-lo bf16x2 words
__device__ __forceinline__ void split2(float x, float y, unsigned& h, unsigned& l) {
    __nv_bfloat16 hx = __float2bfloat16_rn(x);
    __nv_bfloat16 hy = __float2bfloat16_rn(y);
    __nv_bfloat16 lx = __float2bfloat16_rn(x - __bfloat162float(hx));
    __nv_bfloat16 ly = __float2bfloat16_rn(y - __bfloat162float(hy));
    h = pack_bf2(hx, hy);  l = pack_bf2(lx, ly);
}
__device__ __forceinline__ void ldm_x4(unsigned* r, unsigned a) {
    asm volatile("ldmatrix.sync.aligned.m8n8.x4.shared.b16 {%0,%1,%2,%3}, [%4];"
        : "=r"(r[0]), "=r"(r[1]), "=r"(r[2]), "=r"(r[3]) : "r"(a));
}
__device__ __forceinline__ void ldm_x4_t(unsigned* r, unsigned a) {
    asm volatile("ldmatrix.sync.aligned.m8n8.x4.trans.shared.b16 {%0,%1,%2,%3}, [%4];"
        : "=r"(r[0]), "=r"(r[1]), "=r"(r[2]), "=r"(r[3]) : "r"(a));
}
__device__ __forceinline__ void mma_bf16(float* d, const unsigned* a, const unsigned* b) {
    asm volatile(
        "mma.sync.aligned.m16n8k16.row.col.f32.bf16.bf16.f32 "
        "{%0,%1,%2,%3}, {%4,%5,%6,%7}, {%8,%9}, {%0,%1,%2,%3};\n"
        : "+f"(d[0]), "+f"(d[1]), "+f"(d[2]), "+f"(d[3])
        : "r"(a[0]), "r"(a[1]), "r"(a[2]), "r"(a[3]), "r"(b[0]), "r"(b[1]));
}
__device__ __forceinline__ void mma_tf32(float* d, const unsigned* a, const unsigned* b) {
    asm volatile(
        "mma.sync.aligned.m16n8k8.row.col.f32.tf32.tf32.f32 "
        "{%0,%1,%2,%3}, {%4,%5,%6,%7}, {%8,%9}, {%0,%1,%2,%3};\n"
        : "+f"(d[0]), "+f"(d[1]), "+f"(d[2]), "+f"(d[3])
        : "r"(a[0]), "r"(a[1]), "r"(a[2]), "r"(a[3]), "r"(b[0]), "r"(b[1]));
}
__device__ __forceinline__ void cp16(void* dst, const void* src) {
    unsigned d = s2u(dst);
    asm volatile("cp.async.ca.shared.global [%0], [%1], 16;\n" :: "r"(d), "l"(src));
}

// --------------------- fp32 -> bf16 hi/lo split pass -------------------------
__global__ void convert_split(const float4* __restrict__ in,
                              uint2* __restrict__ oh, uint2* __restrict__ ol, int n4)
{
    int i = blockIdx.x * blockDim.x + threadIdx.x;
    if (i >= n4) return;
    float4 v = in[i];
    uint2 H, L;
    split2(v.x, v.y, H.x, L.x);
    split2(v.z, v.w, H.y, L.y);
    oh[i] = H;  ol[i] = L;
}

// ---------------------------------------------------------------------------
// bf16x3 GEMM: C = alpha * A @ B ; A[M,K], B[K,N] pre-split bf16 hi/lo.
// BM=128 BN=128 BK=32, 256 thr (8 warps 4x2), warp tile 32x64, cp.async 2-stage.
// Output: fp32 (Cf) OR bf16 hi/lo (Ch/Cl).
// Smem/stage (bf16 elems): Ah[128][40] Al Bh[32][136] Bl = 18944 (37888 B)
// ---------------------------------------------------------------------------
#define GEMM_STAGE_ELEMS 18944
#define GEMM_SMEM_BYTES  (2 * GEMM_STAGE_ELEMS * 2)   // 75776

__global__ __launch_bounds__(256, 2)
void gemm_bf16x3(const __nv_bfloat16* __restrict__ Ahg, const __nv_bfloat16* __restrict__ Alg,
                 const __nv_bfloat16* __restrict__ Bhg, const __nv_bfloat16* __restrict__ Blg,
                 float* __restrict__ Cf,
                 __nv_bfloat16* __restrict__ Ch, __nv_bfloat16* __restrict__ Cl,
                 int N, int K, float alpha)
{
    extern __shared__ __nv_bfloat16 smg[];
    const int tid = threadIdx.x, lane = tid & 31, wid = tid >> 5;
    const int g = lane >> 2, tg = lane & 3;
    const int wm = (wid >> 1) * 32, wn = (wid & 1) * 64;
    const int bm = blockIdx.y, bn = blockIdx.x;
    const int NT = K >> 5;

    float d[2][8][4];
#pragma unroll
    for (int mt = 0; mt < 2; mt++)
#pragma unroll
        for (int nt = 0; nt < 8; nt++)
#pragma unroll
            for (int i = 0; i < 4; i++) d[mt][nt][i] = 0.f;

    auto issue = [&](int it) {
        __nv_bfloat16* s = smg + (it & 1) * GEMM_STAGE_ELEMS;
        int k0 = it * 32;
#pragma unroll
        for (int j = 0; j < 2; j++) {
            int c = tid + j * 256;
            int ar = c >> 2, ac = (c & 3) << 3;
            size_t ga = (size_t)(bm * 128 + ar) * K + k0 + ac;
            cp16(s + ar * 40 + ac,        Ahg + ga);
            cp16(s + 5120 + ar * 40 + ac, Alg + ga);
            int br = c >> 4, bc = (c & 15) << 3;
            size_t gb = (size_t)(k0 + br) * N + bn * 128 + bc;
            cp16(s + 10240 + br * 136 + bc, Bhg + gb);
            cp16(s + 14592 + br * 136 + bc, Blg + gb);
        }
        asm volatile("cp.async.commit_group;\n");
    };

    issue(0);
    for (int it = 0; it < NT; it++) {
        if (it + 1 < NT) { issue(it + 1); asm volatile("cp.async.wait_group 1;\n"); }
        else             { asm volatile("cp.async.wait_group 0;\n"); }
        __syncthreads();
        const __nv_bfloat16* s = smg + (it & 1) * GEMM_STAGE_ELEMS;

#pragma unroll
        for (int ks = 0; ks < 2; ks++) {
            const int kk = ks * 16;
            unsigned ah[2][4], al[2][4];
            const int arow = lane & 15, acol = kk + ((lane >> 4) << 3);
#pragma unroll
            for (int mt = 0; mt < 2; mt++) {
                ldm_x4(ah[mt], s2u(s + (wm + mt * 16 + arow) * 40 + acol));
                ldm_x4(al[mt], s2u(s + 5120 + (wm + mt * 16 + arow) * 40 + acol));
            }
            const int krow = kk + (lane & 7) + ((lane >> 3) & 1) * 8;
#pragma unroll
            for (int ntp = 0; ntp < 4; ntp++) {
                const int ncol = wn + ntp * 16 + ((lane >> 4) << 3);
                unsigned bh[4], bl[4];
                ldm_x4_t(bh, s2u(s + 10240 + krow * 136 + ncol));
                ldm_x4_t(bl, s2u(s + 14592 + krow * 136 + ncol));
#pragma unroll
                for (int mt = 0; mt < 2; mt++) {
                    mma_bf16(d[mt][2 * ntp],     ah[mt], bh);
                    mma_bf16(d[mt][2 * ntp],     ah[mt], bl);
                    mma_bf16(d[mt][2 * ntp],     al[mt], bh);
                    mma_bf16(d[mt][2 * ntp + 1], ah[mt], bh + 2);
                    mma_bf16(d[mt][2 * ntp + 1], ah[mt], bl + 2);
                    mma_bf16(d[mt][2 * ntp + 1], al[mt], bh + 2);
                }
            }
        }
        __syncthreads();
    }

    // epilogue
#pragma unroll
    for (int mt = 0; mt < 2; mt++) {
        int r0 = bm * 128 + wm + mt * 16 + g;
#pragma unroll
        for (int nt = 0; nt < 8; nt++) {
            int c = bn * 128 + wn + nt * 8 + 2 * tg;
            float v0 = d[mt][nt][0] * alpha, v1 = d[mt][nt][1] * alpha;
            float v2 = d[mt][nt][2] * alpha, v3 = d[mt][nt][3] * alpha;
            if (Cf) {
                *(float2*)(Cf + (size_t)r0 * N + c)       = make_float2(v0, v1);
                *(float2*)(Cf + (size_t)(r0 + 8) * N + c) = make_float2(v2, v3);
            } else {
                unsigned h01, l01, h23, l23;
                split2(v0, v1, h01, l01);
                split2(v2, v3, h23, l23);
                *(unsigned*)(Ch + (size_t)r0 * N + c)       = h01;
                *(unsigned*)(Cl + (size_t)r0 * N + c)       = l01;
                *(unsigned*)(Ch + (size_t)(r0 + 8) * N + c) = h23;
                *(unsigned*)(Cl + (size_t)(r0 + 8) * N + c) = l23;
            }
        }
    }
}

// ---------------------------------------------------------------------------
// Flash attention: Q tile 128 (8 warps x m16), KV tile 64.
// S = QK^T bf16x3 via ldmatrix+mma.  P@V 1x tf32 (accuracy anchor).
// Smem: Qh/Ql[128][72] Kh/Kl[64][72] bf16 ; Vs[64][200] Ps[128][68] f32
// = 141312 B
// ---------------------------------------------------------------------------
#define FLASH_SMEM_BYTES 141312

__global__ __launch_bounds__(256, 1)
void flash_tc(const __nv_bfloat16* __restrict__ Qhg, const __nv_bfloat16* __restrict__ Qlg,
              const __nv_bfloat16* __restrict__ Khg, const __nv_bfloat16* __restrict__ Klg,
              const float* __restrict__ V, float* __restrict__ out)
{
    extern __shared__ char smc[];
    __nv_bfloat16* Qh_s = (__nv_bfloat16*)smc;       // 128*72
    __nv_bfloat16* Ql_s = Qh_s + 128 * 72;
    __nv_bfloat16* Kh_s = Ql_s + 128 * 72;           // 64*72
    __nv_bfloat16* Kl_s = Kh_s + 64 * 72;
    float* Vs = (float*)(Kl_s + 64 * 72);            // 64*200
    float* Ps = Vs + 64 * 200;                       // 128*68

    const int tid = threadIdx.x, lane = tid & 31, wid = tid >> 5;
    const int g = lane >> 2, tg = lane & 3;
    const int w16 = wid * 16;
    const int b = blockIdx.y >> 3, h = blockIdx.y & 7;
    const int q0 = blockIdx.x * 128;

    // Q tile (bf16 hi/lo, direct copy)
#pragma unroll
    for (int r = 0; r < 4; r++) {
        int idx = tid + r * 256;
        int qr = idx >> 3, kc = (idx & 7) << 3;
        size_t go = (size_t)(b * SEQ + q0 + qr) * NQK + h * DK + kc;
        *(uint4*)(Qh_s + qr * 72 + kc) = *(const uint4*)(Qhg + go);
        *(uint4*)(Ql_s + qr * 72 + kc) = *(const uint4*)(Qlg + go);
    }

    float m0 = -1e30f, m1 = -1e30f, l0s = 0.f, l1s = 0.f;
    float o[24][4];
#pragma unroll
    for (int nt = 0; nt < 24; nt++)
#pragma unroll
        for (int i = 0; i < 4; i++) o[nt][i] = 0.f;

    for (int kt = 0; kt < SEQ / 64; kt++) {
        const int kv0 = kt * 64;
        __syncthreads();

        // K tile
#pragma unroll
        for (int r = 0; r < 2; r++) {
            int idx = tid + r * 256;
            int kr = idx >> 3, kc = (idx & 7) << 3;
            size_t go = (size_t)(b * SEQ + kv0 + kr) * NQK + h * DK + kc;
            *(uint4*)(Kh_s + kr * 72 + kc) = *(const uint4*)(Khg + go);
            *(uint4*)(Kl_s + kr * 72 + kc) = *(const uint4*)(Klg + go);
        }
        // V tile (fp32 -> tf32)
#pragma unroll
        for (int r = 0; r < 12; r++) {
            int idx = tid + r * 256;
            int vr = idx / 48, vq = idx % 48;
            float4 v = *(const float4*)(V + (size_t)(b * SEQ + kv0 + vr) * NV + h * DV + vq * 4);
            v.x = __uint_as_float(f2tf(v.x)); v.y = __uint_as_float(f2tf(v.y));
            v.z = __uint_as_float(f2tf(v.z)); v.w = __uint_as_float(f2tf(v.w));
            *(float4*)(Vs + vr * 200 + vq * 4) = v;
        }
        __syncthreads();

        // ---- S = Q @ K^T (bf16x3) ----
        float s[8][4];
#pragma unroll
        for (int nt = 0; nt < 8; nt++)
#pragma unroll
            for (int i = 0; i < 4; i++) s[nt][i] = 0.f;

#pragma unroll
        for (int ks = 0; ks < 4; ks++) {
            const int kk = ks * 16;
            unsigned qh[4], ql[4];
            const int arow = lane & 15, acol = kk + ((lane >> 4) << 3);
            ldm_x4(qh, s2u(Qh_s + (w16 + arow) * 72 + acol));
            ldm_x4(ql, s2u(Ql_s + (w16 + arow) * 72 + acol));
            const int nrow = ((lane >> 4) << 3) + (lane & 7);
            const int kcol = kk + ((lane >> 3) & 1) * 8;
#pragma unroll
            for (int ntp = 0; ntp < 4; ntp++) {
                unsigned kh[4], kl[4];
                ldm_x4(kh, s2u(Kh_s + (ntp * 16 + nrow) * 72 + kcol));
                ldm_x4(kl, s2u(Kl_s + (ntp * 16 + nrow) * 72 + kcol));
                mma_bf16(s[2 * ntp],     qh, kh);
                mma_bf16(s[2 * ntp],     qh, kl);
                mma_bf16(s[2 * ntp],     ql, kh);
                mma_bf16(s[2 * ntp + 1], qh, kh + 2);
                mma_bf16(s[2 * ntp + 1], qh, kl + 2);
                mma_bf16(s[2 * ntp + 1], ql, kh + 2);
            }
        }

        // ---- online softmax (rows g, g+8 of the warp's 16-row band) ----
        float mx0 = -1e30f, mx1 = -1e30f;
#pragma unroll
        for (int nt = 0; nt < 8; nt++) {
            mx0 = fmaxf(mx0, fmaxf(s[nt][0], s[nt][1]));
            mx1 = fmaxf(mx1, fmaxf(s[nt][2], s[nt][3]));
        }
        mx0 = fmaxf(mx0, __shfl_xor_sync(0xffffffffu, mx0, 1));
        mx0 = fmaxf(mx0, __shfl_xor_sync(0xffffffffu, mx0, 2));
        mx1 = fmaxf(mx1, __shfl_xor_sync(0xffffffffu, mx1, 1));
        mx1 = fmaxf(mx1, __shfl_xor_sync(0xffffffffu, mx1, 2));

        float nm0 = fmaxf(m0, mx0), nm1 = fmaxf(m1, mx1);
        float a0 = __expf(m0 - nm0), a1 = __expf(m1 - nm1);
        float sum0 = 0.f, sum1 = 0.f;
#pragma unroll
        for (int nt = 0; nt < 8; nt++) {
            s[nt][0] = __expf(s[nt][0] - nm0); sum0 += s[nt][0];
            s[nt][1] = __expf(s[nt][1] - nm0); sum0 += s[nt][1];
            s[nt][2] = __expf(s[nt][2] - nm1); sum1 += s[nt][2];
            s[nt][3] = __expf(s[nt][3] - nm1); sum1 += s[nt][3];
        }
        sum0 += __shfl_xor_sync(0xffffffffu, sum0, 1);
        sum0 += __shfl_xor_sync(0xffffffffu, sum0, 2);
        sum1 += __shfl_xor_sync(0xffffffffu, sum1, 1);
        sum1 += __shfl_xor_sync(0xffffffffu, sum1, 2);
        l0s = l0s * a0 + sum0;  l1s = l1s * a1 + sum1;
        m0 = nm0;  m1 = nm1;

#pragma unroll
        for (int nt = 0; nt < 24; nt++) {
            o[nt][0] *= a0; o[nt][1] *= a0;
            o[nt][2] *= a1; o[nt][3] *= a1;
        }
#pragma unroll
        for (int nt = 0; nt < 8; nt++) {
            *(float2*)(Ps + (w16 + g) * 68 + nt * 8 + 2 * tg) =
                make_float2(__uint_as_float(f2tf(s[nt][0])), __uint_as_float(f2tf(s[nt][1])));
            *(float2*)(Ps + (w16 + g + 8) * 68 + nt * 8 + 2 * tg) =
                make_float2(__uint_as_float(f2tf(s[nt][2])), __uint_as_float(f2tf(s[nt][3])));
        }
        __syncwarp();

        // ---- O += P @ V (1x tf32) ----
#pragma unroll
        for (int ks = 0; ks < 8; ks++) {
            int kk = ks * 8;
            unsigned ap[4];
            ap[0] = __float_as_uint(Ps[(w16 + g) * 68 + kk + tg]);
            ap[1] = __float_as_uint(Ps[(w16 + g + 8) * 68 + kk + tg]);
            ap[2] = __float_as_uint(Ps[(w16 + g) * 68 + kk + tg + 4]);
            ap[3] = __float_as_uint(Ps[(w16 + g + 8) * 68 + kk + tg + 4]);
#pragma unroll
            for (int nt = 0; nt < 24; nt++) {
                unsigned bv[2];
                bv[0] = __float_as_uint(Vs[(kk + tg) * 200 + nt * 8 + g]);
                bv[1] = __float_as_uint(Vs[(kk + tg + 4) * 200 + nt * 8 + g]);
                mma_tf32(o[nt], ap, bv);
            }
        }
    }

    // epilogue
    float i0 = 1.f / l0s, i1 = 1.f / l1s;
    int r0 = b * SEQ + q0 + w16 + g, r1 = r0 + 8;
#pragma unroll
    for (int nt = 0; nt < 24; nt++) {
        int c = h * DV + nt * 8 + 2 * tg;
        *(float2*)(out + (size_t)r0 * NV + c) = make_float2(o[nt][0] * i0, o[nt][1] * i0);
        *(float2*)(out + (size_t)r1 * NV + c) = make_float2(o[nt][2] * i1, o[nt][3] * i1);
    }
}

// ---------------------------------------------------------------------------
extern "C" void kernel_launch(void* const* d_in, const int* in_sizes, int n_in,
                              void* d_out, int out_size)
{
    const float* X  = (const float*)d_in[0];
    const float* Wq = (const float*)d_in[1];
    const float* Wk = (const float*)d_in[2];
    const float* Wv = (const float*)d_in[3];
    float* out = (float*)d_out;

    void *xh, *xl, *wqh, *wql, *wkh, *wkl, *wvh, *wvl;
    void *qh, *ql, *kh, *kl, *pv;
    cudaGetSymbolAddress(&xh, g_Xh);   cudaGetSymbolAddress(&xl, g_Xl);
    cudaGetSymbolAddress(&wqh, g_Wqh); cudaGetSymbolAddress(&wql, g_Wql);
    cudaGetSymbolAddress(&wkh, g_Wkh); cudaGetSymbolAddress(&wkl, g_Wkl);
    cudaGetSymbolAddress(&wvh, g_Wvh); cudaGetSymbolAddress(&wvl, g_Wvl);
    cudaGetSymbolAddress(&qh, g_Qh);   cudaGetSymbolAddress(&ql, g_Ql);
    cudaGetSymbolAddress(&kh, g_Kh);   cudaGetSymbolAddress(&kl, g_Kl);
    cudaGetSymbolAddress(&pv, g_V);

    static bool attr_set = false;
    if (!attr_set) {
        cudaFuncSetAttribute(gemm_bf16x3,
            cudaFuncAttributeMaxDynamicSharedMemorySize, GEMM_SMEM_BYTES);
        cudaFuncSetAttribute(flash_tc,
            cudaFuncAttributeMaxDynamicSharedMemorySize, FLASH_SMEM_BYTES);
        attr_set = true;
    }

    // split inputs/weights to bf16 hi/lo
    convert_split<<<(MROWS * DMODEL / 4 + 255) / 256, 256>>>(
        (const float4*)X, (uint2*)xh, (uint2*)xl, MROWS * DMODEL / 4);
    convert_split<<<(DMODEL * NQK / 4 + 255) / 256, 256>>>(
        (const float4*)Wq, (uint2*)wqh, (uint2*)wql, DMODEL * NQK / 4);
    convert_split<<<(DMODEL * NQK / 4 + 255) / 256, 256>>>(
        (const float4*)Wk, (uint2*)wkh, (uint2*)wkl, DMODEL * NQK / 4);
    convert_split<<<(DMODEL * NV / 4 + 255) / 256, 256>>>(
        (const float4*)Wv, (uint2*)wvh, (uint2*)wvl, DMODEL * NV / 4);

    // projections: Q,K -> bf16 hi/lo (scale folded into Q), V -> fp32
    dim3 gqk(NQK / 128, MROWS / 128);   // (4, 48)
    gemm_bf16x3<<<gqk, 256, GEMM_SMEM_BYTES>>>(
        (const __nv_bfloat16*)xh, (const __nv_bfloat16*)xl,
        (const __nv_bfloat16*)wqh, (const __nv_bfloat16*)wql,
        nullptr, (__nv_bfloat16*)qh, (__nv_bfloat16*)ql, NQK, DMODEL, 0.125f);
    gemm_bf16x3<<<gqk, 256, GEMM_SMEM_BYTES>>>(
        (const __nv_bfloat16*)xh, (const __nv_bfloat16*)xl,
        (const __nv_bfloat16*)wkh, (const __nv_bfloat16*)wkl,
        nullptr, (__nv_bfloat16*)kh, (__nv_bfloat16*)kl, NQK, DMODEL, 1.0f);
    dim3 gv(NV / 128, MROWS / 128);     // (12, 48)
    gemm_bf16x3<<<gv, 256, GEMM_SMEM_BYTES>>>(
        (const __nv_bfloat16*)xh, (const __nv_bfloat16*)xl,
        (const __nv_bfloat16*)wvh, (const __nv_bfloat16*)wvl,
        (float*)pv, nullptr, nullptr, NV, DMODEL, 1.0f);

    flash_tc<<<dim3(SEQ / 128, BATCH * HEADS), 256, FLASH_SMEM_BYTES>>>(
        (const __nv_bfloat16*)qh, (const __nv_bfloat16*)ql,
        (const __nv_bfloat16*)kh, (const __nv_bfloat16*)kl,
        (const float*)pv, out);
}

// round 6
// speedup vs baseline: 3.1682x; 1.1018x over previous
#include <cuda_runtime.h>
#include <cuda_bf16.h>
#include <cstdint>

#define HEADS   8
#define DK      64
#define DV      192
#define BATCH   4
#define SEQ     1536
#define DMODEL  1536
#define MROWS   (BATCH*SEQ)          // 6144
#define NQK     (HEADS*DK)           // 512
#define NV      (HEADS*DV)           // 1536

// ------------------------- global scratch (no allocs) -----------------------
__device__ __nv_bfloat16 g_Xh[MROWS * DMODEL], g_Xl[MROWS * DMODEL];
__device__ __nv_bfloat16 g_Wqh[DMODEL * NQK], g_Wql[DMODEL * NQK];
__device__ __nv_bfloat16 g_Wkh[DMODEL * NQK], g_Wkl[DMODEL * NQK];
__device__ __nv_bfloat16 g_Wvh[DMODEL * NV],  g_Wvl[DMODEL * NV];
__device__ __nv_bfloat16 g_Qh[MROWS * NQK],   g_Ql[MROWS * NQK];
__device__ __nv_bfloat16 g_Kh[MROWS * NQK],   g_Kl[MROWS * NQK];
__device__ float         g_V [MROWS * NV];    // tf32-rounded values

// ------------------------------- helpers ------------------------------------
__device__ __forceinline__ unsigned s2u(const void* p) {
    return (unsigned)__cvta_generic_to_shared(p);
}
__device__ __forceinline__ unsigned f2tf(float x) {
    unsigned u; asm("cvt.rna.tf32.f32 %0, %1;" : "=r"(u) : "f"(x)); return u;
}
__device__ __forceinline__ unsigned pack_bf2(__nv_bfloat16 a, __nv_bfloat16 b) {
    return (unsigned)__bfloat16_as_ushort(a) | ((unsigned)__bfloat16_as_ushort(b) << 16);
}
__device__ __forceinline__ void split2(float x, float y, unsigned& h, unsigned& l) {
    __nv_bfloat16 hx = __float2bfloat16_rn(x);
    __nv_bfloat16 hy = __float2bfloat16_rn(y);
    __nv_bfloat16 lx = __float2bfloat16_rn(x - __bfloat162float(hx));
    __nv_bfloat16 ly = __float2bfloat16_rn(y - __bfloat162float(hy));
    h = pack_bf2(hx, hy);  l = pack_bf2(lx, ly);
}
__device__ __forceinline__ void ldm_x4(unsigned* r, unsigned a) {
    asm volatile("ldmatrix.sync.aligned.m8n8.x4.shared.b16 {%0,%1,%2,%3}, [%4];"
        : "=r"(r[0]), "=r"(r[1]), "=r"(r[2]), "=r"(r[3]) : "r"(a));
}
__device__ __forceinline__ void ldm_x4_t(unsigned* r, unsigned a) {
    asm volatile("ldmatrix.sync.aligned.m8n8.x4.trans.shared.b16 {%0,%1,%2,%3}, [%4];"
        : "=r"(r[0]), "=r"(r[1]), "=r"(r[2]), "=r"(r[3]) : "r"(a));
}
__device__ __forceinline__ void mma_bf16(float* d, const unsigned* a, const unsigned* b) {
    asm volatile(
        "mma.sync.aligned.m16n8k16.row.col.f32.bf16.bf16.f32 "
        "{%0,%1,%2,%3}, {%4,%5,%6,%7}, {%8,%9}, {%0,%1,%2,%3};\n"
        : "+f"(d[0]), "+f"(d[1]), "+f"(d[2]), "+f"(d[3])
        : "r"(a[0]), "r"(a[1]), "r"(a[2]), "r"(a[3]), "r"(b[0]), "r"(b[1]));
}
__device__ __forceinline__ void mma_tf32(float* d, const unsigned* a, const unsigned* b) {
    asm volatile(
        "mma.sync.aligned.m16n8k8.row.col.f32.tf32.tf32.f32 "
        "{%0,%1,%2,%3}, {%4,%5,%6,%7}, {%8,%9}, {%0,%1,%2,%3};\n"
        : "+f"(d[0]), "+f"(d[1]), "+f"(d[2]), "+f"(d[3])
        : "r"(a[0]), "r"(a[1]), "r"(a[2]), "r"(a[3]), "r"(b[0]), "r"(b[1]));
}
__device__ __forceinline__ void cp16(void* dst, const void* src) {
    unsigned d = s2u(dst);
    asm volatile("cp.async.ca.shared.global [%0], [%1], 16;\n" :: "r"(d), "l"(src));
}
__device__ __forceinline__ void cp_commit() { asm volatile("cp.async.commit_group;\n"); }
__device__ __forceinline__ void cp_wait0()  { asm volatile("cp.async.wait_group 0;\n" ::: "memory"); }
__device__ __forceinline__ void cp_wait1()  { asm volatile("cp.async.wait_group 1;\n" ::: "memory"); }

// --------------------- fp32 -> bf16 hi/lo split ------------------------------
__global__ void convert_split(const float4* __restrict__ in,
                              uint2* __restrict__ oh, uint2* __restrict__ ol, int n4)
{
    int i = blockIdx.x * blockDim.x + threadIdx.x;
    if (i >= n4) return;
    float4 v = in[i];
    uint2 H, L;
    split2(v.x, v.y, H.x, L.x);
    split2(v.z, v.w, H.y, L.y);
    oh[i] = H;  ol[i] = L;
}

// ---------------------------------------------------------------------------
// Fused projection GEMM (bf16x3, mma.sync): one kernel computes Q, K, V.
// Segment by bn: bn<4 -> Q (N=512, alpha=0.125, bf16 hi/lo out)
//                bn<8 -> K (N=512, bf16 hi/lo out)
//                else -> V (N=1536, fp32 tf32-rounded out)
// BM=128 BN=128 BK=32, 256 thr (8 warps 4x2), warp tile 32x64, cp.async 2-stage.
// Smem/stage (bf16 elems): Ah[128][40] Al Bh[32][136] Bl = 18944 (37888 B)
// ---------------------------------------------------------------------------
#define GEMM_STAGE_ELEMS 18944
#define GEMM_SMEM_BYTES  (2 * GEMM_STAGE_ELEMS * 2)   // 75776

__global__ __launch_bounds__(256, 2)
void gemm_fused(const __nv_bfloat16* __restrict__ Ahg, const __nv_bfloat16* __restrict__ Alg,
                const __nv_bfloat16* __restrict__ Wqh_, const __nv_bfloat16* __restrict__ Wql_,
                const __nv_bfloat16* __restrict__ Wkh_, const __nv_bfloat16* __restrict__ Wkl_,
                const __nv_bfloat16* __restrict__ Wvh_, const __nv_bfloat16* __restrict__ Wvl_,
                __nv_bfloat16* __restrict__ Qh_, __nv_bfloat16* __restrict__ Ql_,
                __nv_bfloat16* __restrict__ Kh_, __nv_bfloat16* __restrict__ Kl_,
                float* __restrict__ Vf_)
{
    extern __shared__ __nv_bfloat16 smg[];
    const int tid = threadIdx.x, lane = tid & 31, wid = tid >> 5;
    const int g = lane >> 2, tg = lane & 3;
    const int wm = (wid >> 1) * 32, wn = (wid & 1) * 64;
    const int bm = blockIdx.y, bn_g = blockIdx.x;
    const int K = DMODEL;
    const int NT = K >> 5;

    // segment dispatch (uniform per block)
    const __nv_bfloat16 *Bhg, *Blg;
    int Nb, bnn, seg;
    if (bn_g < 4)      { Bhg = Wqh_; Blg = Wql_; Nb = NQK; bnn = bn_g;     seg = 0; }
    else if (bn_g < 8) { Bhg = Wkh_; Blg = Wkl_; Nb = NQK; bnn = bn_g - 4; seg = 1; }
    else               { Bhg = Wvh_; Blg = Wvl_; Nb = NV;  bnn = bn_g - 8; seg = 2; }
    const float alpha = (seg == 0) ? 0.125f : 1.0f;

    float d[2][8][4];
#pragma unroll
    for (int mt = 0; mt < 2; mt++)
#pragma unroll
        for (int nt = 0; nt < 8; nt++)
#pragma unroll
            for (int i = 0; i < 4; i++) d[mt][nt][i] = 0.f;

    auto issue = [&](int it) {
        __nv_bfloat16* s = smg + (it & 1) * GEMM_STAGE_ELEMS;
        int k0 = it * 32;
#pragma unroll
        for (int j = 0; j < 2; j++) {
            int c = tid + j * 256;
            int ar = c >> 2, ac = (c & 3) << 3;
            size_t ga = (size_t)(bm * 128 + ar) * K + k0 + ac;
            cp16(s + ar * 40 + ac,        Ahg + ga);
            cp16(s + 5120 + ar * 40 + ac, Alg + ga);
            int br = c >> 4, bc = (c & 15) << 3;
            size_t gb = (size_t)(k0 + br) * Nb + bnn * 128 + bc;
            cp16(s + 10240 + br * 136 + bc, Bhg + gb);
            cp16(s + 14592 + br * 136 + bc, Blg + gb);
        }
        cp_commit();
    };

    issue(0);
    for (int it = 0; it < NT; it++) {
        if (it + 1 < NT) { issue(it + 1); cp_wait1(); }
        else             { cp_wait0(); }
        __syncthreads();
        const __nv_bfloat16* s = smg + (it & 1) * GEMM_STAGE_ELEMS;

#pragma unroll
        for (int ks = 0; ks < 2; ks++) {
            const int kk = ks * 16;
            unsigned ah[2][4], al[2][4];
            const int arow = lane & 15, acol = kk + ((lane >> 4) << 3);
#pragma unroll
            for (int mt = 0; mt < 2; mt++) {
                ldm_x4(ah[mt], s2u(s + (wm + mt * 16 + arow) * 40 + acol));
                ldm_x4(al[mt], s2u(s + 5120 + (wm + mt * 16 + arow) * 40 + acol));
            }
            const int krow = kk + (lane & 7) + ((lane >> 3) & 1) * 8;
#pragma unroll
            for (int ntp = 0; ntp < 4; ntp++) {
                const int ncol = wn + ntp * 16 + ((lane >> 4) << 3);
                unsigned bh[4], bl[4];
                ldm_x4_t(bh, s2u(s + 10240 + krow * 136 + ncol));
                ldm_x4_t(bl, s2u(s + 14592 + krow * 136 + ncol));
#pragma unroll
                for (int mt = 0; mt < 2; mt++) {
                    mma_bf16(d[mt][2 * ntp],     ah[mt], bh);
                    mma_bf16(d[mt][2 * ntp],     ah[mt], bl);
                    mma_bf16(d[mt][2 * ntp],     al[mt], bh);
                    mma_bf16(d[mt][2 * ntp + 1], ah[mt], bh + 2);
                    mma_bf16(d[mt][2 * ntp + 1], ah[mt], bl + 2);
                    mma_bf16(d[mt][2 * ntp + 1], al[mt], bh + 2);
                }
            }
        }
        __syncthreads();
    }

    // epilogue (per segment)
#pragma unroll
    for (int mt = 0; mt < 2; mt++) {
        int r0 = bm * 128 + wm + mt * 16 + g;
#pragma unroll
        for (int nt = 0; nt < 8; nt++) {
            int c = bnn * 128 + wn + nt * 8 + 2 * tg;
            float v0 = d[mt][nt][0] * alpha, v1 = d[mt][nt][1] * alpha;
            float v2 = d[mt][nt][2] * alpha, v3 = d[mt][nt][3] * alpha;
            if (seg == 2) {
                // V: store tf32-rounded fp32 (flash consumes bits directly)
                *(float2*)(Vf_ + (size_t)r0 * NV + c) =
                    make_float2(__uint_as_float(f2tf(v0)), __uint_as_float(f2tf(v1)));
                *(float2*)(Vf_ + (size_t)(r0 + 8) * NV + c) =
                    make_float2(__uint_as_float(f2tf(v2)), __uint_as_float(f2tf(v3)));
            } else {
                __nv_bfloat16* Ch = (seg == 0) ? Qh_ : Kh_;
                __nv_bfloat16* Cl = (seg == 0) ? Ql_ : Kl_;
                unsigned h01, l01, h23, l23;
                split2(v0, v1, h01, l01);
                split2(v2, v3, h23, l23);
                *(unsigned*)(Ch + (size_t)r0 * NQK + c)       = h01;
                *(unsigned*)(Cl + (size_t)r0 * NQK + c)       = l01;
                *(unsigned*)(Ch + (size_t)(r0 + 8) * NQK + c) = h23;
                *(unsigned*)(Cl + (size_t)(r0 + 8) * NQK + c) = l23;
            }
        }
    }
}

// ---------------------------------------------------------------------------
// Flash attention: Q tile 128 (8 warps x m16), KV tile 64, cp.async 2-stage KV.
// S = QK^T bf16x3 (ldmatrix+mma).  P@V 1x tf32 (V pre-rounded to tf32).
// Smem bytes: Qh/Ql 36864 | stage0 69632 | stage1 69632 | Ps 34816 = 210944
//   stage: Kh[64][72] 9216 | Kl 9216 | Vs[64][200] f32 51200
// ---------------------------------------------------------------------------
#define FLASH_STAGE_BYTES 69632
#define FLASH_SMEM_BYTES  210944

__global__ __launch_bounds__(256, 1)
void flash_tc(const __nv_bfloat16* __restrict__ Qhg, const __nv_bfloat16* __restrict__ Qlg,
              const __nv_bfloat16* __restrict__ Khg, const __nv_bfloat16* __restrict__ Klg,
              const float* __restrict__ V, float* __restrict__ out)
{
    extern __shared__ char smc[];
    __nv_bfloat16* Qh_s = (__nv_bfloat16*)smc;               // 128*72
    __nv_bfloat16* Ql_s = (__nv_bfloat16*)(smc + 18432);
    float* Ps = (float*)(smc + 176128);                      // 128*68

    const int tid = threadIdx.x, lane = tid & 31, wid = tid >> 5;
    const int g = lane >> 2, tg = lane & 3;
    const int w16 = wid * 16;
    const int b = blockIdx.y >> 3, h = blockIdx.y & 7;
    const int q0 = blockIdx.x * 128;
    const int NT = SEQ / 64;

    // Q tile (direct, once)
#pragma unroll
    for (int r = 0; r < 4; r++) {
        int idx = tid + r * 256;
        int qr = idx >> 3, kc = (idx & 7) << 3;
        size_t go = (size_t)(b * SEQ + q0 + qr) * NQK + h * DK + kc;
        *(uint4*)(Qh_s + qr * 72 + kc) = *(const uint4*)(Qhg + go);
        *(uint4*)(Ql_s + qr * 72 + kc) = *(const uint4*)(Qlg + go);
    }

    auto issue_kv = [&](int kt) {
        char* st = smc + 36864 + (kt & 1) * FLASH_STAGE_BYTES;
        const int kv0 = kt * 64;
#pragma unroll
        for (int i = 0; i < 2; i++) {            // K hi/lo: 64 rows x 8 chunks
            int idx = tid + i * 256;
            int r = idx >> 3, q = idx & 7;
            size_t go = (size_t)(b * SEQ + kv0 + r) * NQK + h * DK + q * 8;
            cp16(st + r * 144 + q * 16, Khg + go);
            cp16(st + 9216 + r * 144 + q * 16, Klg + go);
        }
#pragma unroll
        for (int i = 0; i < 12; i++) {           // V: 64 rows x 48 chunks of 16B
            int idx = tid + i * 256;
            int r = idx / 48, cq = idx % 48;
            cp16(st + 18432 + r * 800 + cq * 16,
                 V + (size_t)(b * SEQ + kv0 + r) * NV + h * DV + cq * 4);
        }
        cp_commit();
    };

    float m0 = -1e30f, m1 = -1e30f, l0s = 0.f, l1s = 0.f;
    float o[24][4];
#pragma unroll
    for (int nt = 0; nt < 24; nt++)
#pragma unroll
        for (int i = 0; i < 4; i++) o[nt][i] = 0.f;

    issue_kv(0);
    for (int kt = 0; kt < NT; kt++) {
        if (kt + 1 < NT) { issue_kv(kt + 1); cp_wait1(); }
        else             { cp_wait0(); }
        __syncthreads();

        char* st = smc + 36864 + (kt & 1) * FLASH_STAGE_BYTES;
        __nv_bfloat16* Kh_s = (__nv_bfloat16*)st;
        __nv_bfloat16* Kl_s = (__nv_bfloat16*)(st + 9216);
        float* Vs = (float*)(st + 18432);

        // ---- S = Q @ K^T (bf16x3) ----
        float s[8][4];
#pragma unroll
        for (int nt = 0; nt < 8; nt++)
#pragma unroll
            for (int i = 0; i < 4; i++) s[nt][i] = 0.f;

#pragma unroll
        for (int ks = 0; ks < 4; ks++) {
            const int kk = ks * 16;
            unsigned qh[4], ql[4];
            const int arow = lane & 15, acol = kk + ((lane >> 4) << 3);
            ldm_x4(qh, s2u(Qh_s + (w16 + arow) * 72 + acol));
            ldm_x4(ql, s2u(Ql_s + (w16 + arow) * 72 + acol));
            const int nrow = ((lane >> 4) << 3) + (lane & 7);
            const int kcol = kk + ((lane >> 3) & 1) * 8;
#pragma unroll
            for (int ntp = 0; ntp < 4; ntp++) {
                unsigned kh[4], kl[4];
                ldm_x4(kh, s2u(Kh_s + (ntp * 16 + nrow) * 72 + kcol));
                ldm_x4(kl, s2u(Kl_s + (ntp * 16 + nrow) * 72 + kcol));
                mma_bf16(s[2 * ntp],     qh, kh);
                mma_bf16(s[2 * ntp],     qh, kl);
                mma_bf16(s[2 * ntp],     ql, kh);
                mma_bf16(s[2 * ntp + 1], qh, kh + 2);
                mma_bf16(s[2 * ntp + 1], qh, kl + 2);
                mma_bf16(s[2 * ntp + 1], ql, kh + 2);
            }
        }

        // ---- online softmax ----
        float mx0 = -1e30f, mx1 = -1e30f;
#pragma unroll
        for (int nt = 0; nt < 8; nt++) {
            mx0 = fmaxf(mx0, fmaxf(s[nt][0], s[nt][1]));
            mx1 = fmaxf(mx1, fmaxf(s[nt][2], s[nt][3]));
        }
        mx0 = fmaxf(mx0, __shfl_xor_sync(0xffffffffu, mx0, 1));
        mx0 = fmaxf(mx0, __shfl_xor_sync(0xffffffffu, mx0, 2));
        mx1 = fmaxf(mx1, __shfl_xor_sync(0xffffffffu, mx1, 1));
        mx1 = fmaxf(mx1, __shfl_xor_sync(0xffffffffu, mx1, 2));

        float nm0 = fmaxf(m0, mx0), nm1 = fmaxf(m1, mx1);
        float a0 = __expf(m0 - nm0), a1 = __expf(m1 - nm1);
        float sum0 = 0.f, sum1 = 0.f;
#pragma unroll
        for (int nt = 0; nt < 8; nt++) {
            s[nt][0] = __expf(s[nt][0] - nm0); sum0 += s[nt][0];
            s[nt][1] = __expf(s[nt][1] - nm0); sum0 += s[nt][1];
            s[nt][2] = __expf(s[nt][2] - nm1); sum1 += s[nt][2];
            s[nt][3] = __expf(s[nt][3] - nm1); sum1 += s[nt][3];
        }
        sum0 += __shfl_xor_sync(0xffffffffu, sum0, 1);
        sum0 += __shfl_xor_sync(0xffffffffu, sum0, 2);
        sum1 += __shfl_xor_sync(0xffffffffu, sum1, 1);
        sum1 += __shfl_xor_sync(0xffffffffu, sum1, 2);
        l0s = l0s * a0 + sum0;  l1s = l1s * a1 + sum1;
        m0 = nm0;  m1 = nm1;

#pragma unroll
        for (int nt = 0; nt < 24; nt++) {
            o[nt][0] *= a0; o[nt][1] *= a0;
            o[nt][2] *= a1; o[nt][3] *= a1;
        }
#pragma unroll
        for (int nt = 0; nt < 8; nt++) {
            *(float2*)(Ps + (w16 + g) * 68 + nt * 8 + 2 * tg) =
                make_float2(__uint_as_float(f2tf(s[nt][0])), __uint_as_float(f2tf(s[nt][1])));
            *(float2*)(Ps + (w16 + g + 8) * 68 + nt * 8 + 2 * tg) =
                make_float2(__uint_as_float(f2tf(s[nt][2])), __uint_as_float(f2tf(s[nt][3])));
        }
        __syncwarp();

        // ---- O += P @ V (1x tf32) ----
#pragma unroll
        for (int ks = 0; ks < 8; ks++) {
            int kk = ks * 8;
            unsigned ap[4];
            ap[0] = __float_as_uint(Ps[(w16 + g) * 68 + kk + tg]);
            ap[1] = __float_as_uint(Ps[(w16 + g + 8) * 68 + kk + tg]);
            ap[2] = __float_as_uint(Ps[(w16 + g) * 68 + kk + tg + 4]);
            ap[3] = __float_as_uint(Ps[(w16 + g + 8) * 68 + kk + tg + 4]);
#pragma unroll
            for (int nt = 0; nt < 24; nt++) {
                unsigned bv[2];
                bv[0] = __float_as_uint(Vs[(kk + tg) * 200 + nt * 8 + g]);
                bv[1] = __float_as_uint(Vs[(kk + tg + 4) * 200 + nt * 8 + g]);
                mma_tf32(o[nt], ap, bv);
            }
        }
        __syncthreads();   // protect stage buffer before next issue overwrites
    }

    // epilogue
    float i0 = 1.f / l0s, i1 = 1.f / l1s;
    int r0 = b * SEQ + q0 + w16 + g, r1 = r0 + 8;
#pragma unroll
    for (int nt = 0; nt < 24; nt++) {
        int c = h * DV + nt * 8 + 2 * tg;
        *(float2*)(out + (size_t)r0 * NV + c) = make_float2(o[nt][0] * i0, o[nt][1] * i0);
        *(float2*)(out + (size_t)r1 * NV + c) = make_float2(o[nt][2] * i1, o[nt][3] * i1);
    }
}

// ---------------------------------------------------------------------------
extern "C" void kernel_launch(void* const* d_in, const int* in_sizes, int n_in,
                              void* d_out, int out_size)
{
    const float* X  = (const float*)d_in[0];
    const float* Wq = (const float*)d_in[1];
    const float* Wk = (const float*)d_in[2];
    const float* Wv = (const float*)d_in[3];
    float* out = (float*)d_out;

    void *xh, *xl, *wqh, *wql, *wkh, *wkl, *wvh, *wvl;
    void *qh, *ql, *kh, *kl, *pv;
    cudaGetSymbolAddress(&xh, g_Xh);   cudaGetSymbolAddress(&xl, g_Xl);
    cudaGetSymbolAddress(&wqh, g_Wqh); cudaGetSymbolAddress(&wql, g_Wql);
    cudaGetSymbolAddress(&wkh, g_Wkh); cudaGetSymbolAddress(&wkl, g_Wkl);
    cudaGetSymbolAddress(&wvh, g_Wvh); cudaGetSymbolAddress(&wvl, g_Wvl);
    cudaGetSymbolAddress(&qh, g_Qh);   cudaGetSymbolAddress(&ql, g_Ql);
    cudaGetSymbolAddress(&kh, g_Kh);   cudaGetSymbolAddress(&kl, g_Kl);
    cudaGetSymbolAddress(&pv, g_V);

    static bool attr_set = false;
    if (!attr_set) {
        cudaFuncSetAttribute(gemm_fused,
            cudaFuncAttributeMaxDynamicSharedMemorySize, GEMM_SMEM_BYTES);
        cudaFuncSetAttribute(flash_tc,
            cudaFuncAttributeMaxDynamicSharedMemorySize, FLASH_SMEM_BYTES);
        attr_set = true;
    }

    // split X and weights to bf16 hi/lo (original layouts)
    convert_split<<<(MROWS * DMODEL / 4 + 255) / 256, 256>>>(
        (const float4*)X, (uint2*)xh, (uint2*)xl, MROWS * DMODEL / 4);
    convert_split<<<(DMODEL * NQK / 4 + 255) / 256, 256>>>(
        (const float4*)Wq, (uint2*)wqh, (uint2*)wql, DMODEL * NQK / 4);
    convert_split<<<(DMODEL * NQK / 4 + 255) / 256, 256>>>(
        (const float4*)Wk, (uint2*)wkh, (uint2*)wkl, DMODEL * NQK / 4);
    convert_split<<<(DMODEL * NV / 4 + 255) / 256, 256>>>(
        (const float4*)Wv, (uint2*)wvh, (uint2*)wvl, DMODEL * NV / 4);

    // one fused projection GEMM: Q | K | V
    gemm_fused<<<dim3(20, MROWS / 128), 256, GEMM_SMEM_BYTES>>>(
        (const __nv_bfloat16*)xh, (const __nv_bfloat16*)xl,
        (const __nv_bfloat16*)wqh, (const __nv_bfloat16*)wql,
        (const __nv_bfloat16*)wkh, (const __nv_bfloat16*)wkl,
        (const __nv_bfloat16*)wvh, (const __nv_bfloat16*)wvl,
        (__nv_bfloat16*)qh, (__nv_bfloat16*)ql,
        (__nv_bfloat16*)kh, (__nv_bfloat16*)kl,
        (float*)pv);

    flash_tc<<<dim3(SEQ / 128, BATCH * HEADS), 256, FLASH_SMEM_BYTES>>>(
        (const __nv_bfloat16*)qh, (const __nv_bfloat16*)ql,
        (const __nv_bfloat16*)kh, (const __nv_bfloat16*)kl,
        (const float*)pv, out);
}

// round 7
// speedup vs baseline: 4.8627x; 1.5349x over previous
#include <cuda_runtime.h>
#include <cuda_fp16.h>
#include <cstdint>

#define HEADS   8
#define DK      64
#define DV      192
#define BATCH   4
#define SEQ     1536
#define DMODEL  1536
#define MROWS   (BATCH*SEQ)          // 6144
#define NQK     (HEADS*DK)           // 512
#define NV      (HEADS*DV)           // 1536

// ------------------------- global scratch (no allocs) -----------------------
__device__ __half g_Xh[MROWS * DMODEL], g_Xl[MROWS * DMODEL];   // X hi/lo fp16
__device__ __half g_Wq[DMODEL * NQK];                            // W single fp16
__device__ __half g_Wk[DMODEL * NQK];
__device__ __half g_Wv[DMODEL * NV];
__device__ __half g_Q [MROWS * NQK];                             // Q single fp16 (pre-scaled)
__device__ __half g_Kh[MROWS * NQK], g_Kl[MROWS * NQK];          // K hi/lo fp16
__device__ __half g_V [MROWS * NV];                              // V single fp16

// ------------------------------- helpers ------------------------------------
__device__ __forceinline__ unsigned s2u(const void* p) {
    return (unsigned)__cvta_generic_to_shared(p);
}
__device__ __forceinline__ unsigned packh2(float a, float b) {
    __half ha = __float2half_rn(a), hb = __float2half_rn(b);
    return (unsigned)__half_as_ushort(ha) | ((unsigned)__half_as_ushort(hb) << 16);
}
// split two floats into packed-hi and packed-lo fp16x2 words
__device__ __forceinline__ void split2h(float x, float y, unsigned& h, unsigned& l) {
    __half hx = __float2half_rn(x), hy = __float2half_rn(y);
    __half lx = __float2half_rn(x - __half2float(hx));
    __half ly = __float2half_rn(y - __half2float(hy));
    h = (unsigned)__half_as_ushort(hx) | ((unsigned)__half_as_ushort(hy) << 16);
    l = (unsigned)__half_as_ushort(lx) | ((unsigned)__half_as_ushort(ly) << 16);
}
__device__ __forceinline__ void ldm_x4(unsigned* r, unsigned a) {
    asm volatile("ldmatrix.sync.aligned.m8n8.x4.shared.b16 {%0,%1,%2,%3}, [%4];"
        : "=r"(r[0]), "=r"(r[1]), "=r"(r[2]), "=r"(r[3]) : "r"(a));
}
__device__ __forceinline__ void ldm_x4_t(unsigned* r, unsigned a) {
    asm volatile("ldmatrix.sync.aligned.m8n8.x4.trans.shared.b16 {%0,%1,%2,%3}, [%4];"
        : "=r"(r[0]), "=r"(r[1]), "=r"(r[2]), "=r"(r[3]) : "r"(a));
}
__device__ __forceinline__ void mma_f16(float* d, const unsigned* a, const unsigned* b) {
    asm volatile(
        "mma.sync.aligned.m16n8k16.row.col.f32.f16.f16.f32 "
        "{%0,%1,%2,%3}, {%4,%5,%6,%7}, {%8,%9}, {%0,%1,%2,%3};\n"
        : "+f"(d[0]), "+f"(d[1]), "+f"(d[2]), "+f"(d[3])
        : "r"(a[0]), "r"(a[1]), "r"(a[2]), "r"(a[3]), "r"(b[0]), "r"(b[1]));
}
__device__ __forceinline__ void cp16(void* dst, const void* src) {
    unsigned d = s2u(dst);
    asm volatile("cp.async.ca.shared.global [%0], [%1], 16;\n" :: "r"(d), "l"(src));
}
__device__ __forceinline__ void cp_commit() { asm volatile("cp.async.commit_group;\n"); }
__device__ __forceinline__ void cp_wait0()  { asm volatile("cp.async.wait_group 0;\n" ::: "memory"); }
__device__ __forceinline__ void cp_wait1()  { asm volatile("cp.async.wait_group 1;\n" ::: "memory"); }

// --------------------- fp32 -> fp16 hi/lo split (X) --------------------------
__global__ void convert_split_h(const float4* __restrict__ in,
                                uint2* __restrict__ oh, uint2* __restrict__ ol, int n4)
{
    int i = blockIdx.x * blockDim.x + threadIdx.x;
    if (i >= n4) return;
    float4 v = in[i];
    uint2 H, L;
    split2h(v.x, v.y, H.x, L.x);
    split2h(v.z, v.w, H.y, L.y);
    oh[i] = H;  ol[i] = L;
}
// --------------------- fp32 -> fp16 single convert (W) -----------------------
__global__ void convert_h(const float4* __restrict__ in, uint2* __restrict__ o, int n4)
{
    int i = blockIdx.x * blockDim.x + threadIdx.x;
    if (i >= n4) return;
    float4 v = in[i];
    uint2 H;
    H.x = packh2(v.x, v.y);
    H.y = packh2(v.z, v.w);
    o[i] = H;
}

// ---------------------------------------------------------------------------
// Fused projection GEMM (fp16, 2-product): one kernel computes Q, K, V.
// C = alpha * (Xh + Xl) @ W.  Segments: bn<4 -> Q ; bn<8 -> K ; else -> V.
// BM=128 BN=128 BK=32, 256 thr (8 warps 4x2), warp tile 32x64, cp.async 2-stage.
// Smem/stage (halfs): Ah[128][40] | Al[128][40] | B[32][136] = 14592 (29184 B)
// ---------------------------------------------------------------------------
#define GEMM_STAGE_ELEMS 14592
#define GEMM_SMEM_BYTES  (2 * GEMM_STAGE_ELEMS * 2)   // 58368

__global__ __launch_bounds__(256, 2)
void gemm_fused(const __half* __restrict__ Ahg, const __half* __restrict__ Alg,
                const __half* __restrict__ Wq_, const __half* __restrict__ Wk_,
                const __half* __restrict__ Wv_,
                __half* __restrict__ Q_, __half* __restrict__ Kh_,
                __half* __restrict__ Kl_, __half* __restrict__ V_)
{
    extern __shared__ __half smg[];
    const int tid = threadIdx.x, lane = tid & 31, wid = tid >> 5;
    const int g = lane >> 2, tg = lane & 3;
    const int wm = (wid >> 1) * 32, wn = (wid & 1) * 64;
    const int bm = blockIdx.y, bn_g = blockIdx.x;
    const int K = DMODEL;
    const int NT = K >> 5;

    const __half* Bg;
    int Nb, bnn, seg;
    if (bn_g < 4)      { Bg = Wq_; Nb = NQK; bnn = bn_g;     seg = 0; }
    else if (bn_g < 8) { Bg = Wk_; Nb = NQK; bnn = bn_g - 4; seg = 1; }
    else               { Bg = Wv_; Nb = NV;  bnn = bn_g - 8; seg = 2; }
    const float alpha = (seg == 0) ? 0.125f : 1.0f;

    float d[2][8][4];
#pragma unroll
    for (int mt = 0; mt < 2; mt++)
#pragma unroll
        for (int nt = 0; nt < 8; nt++)
#pragma unroll
            for (int i = 0; i < 4; i++) d[mt][nt][i] = 0.f;

    auto issue = [&](int it) {
        __half* s = smg + (it & 1) * GEMM_STAGE_ELEMS;
        int k0 = it * 32;
#pragma unroll
        for (int j = 0; j < 2; j++) {
            int c = tid + j * 256;
            int ar = c >> 2, ac = (c & 3) << 3;
            size_t ga = (size_t)(bm * 128 + ar) * K + k0 + ac;
            cp16(s + ar * 40 + ac,        Ahg + ga);
            cp16(s + 5120 + ar * 40 + ac, Alg + ga);
            int br = c >> 4, bc = (c & 15) << 3;
            size_t gb = (size_t)(k0 + br) * Nb + bnn * 128 + bc;
            cp16(s + 10240 + br * 136 + bc, Bg + gb);
        }
        cp_commit();
    };

    issue(0);
    for (int it = 0; it < NT; it++) {
        if (it + 1 < NT) { issue(it + 1); cp_wait1(); }
        else             { cp_wait0(); }
        __syncthreads();
        const __half* s = smg + (it & 1) * GEMM_STAGE_ELEMS;

#pragma unroll
        for (int ks = 0; ks < 2; ks++) {
            const int kk = ks * 16;
            unsigned ah[2][4], al[2][4];
            const int arow = lane & 15, acol = kk + ((lane >> 4) << 3);
#pragma unroll
            for (int mt = 0; mt < 2; mt++) {
                ldm_x4(ah[mt], s2u(s + (wm + mt * 16 + arow) * 40 + acol));
                ldm_x4(al[mt], s2u(s + 5120 + (wm + mt * 16 + arow) * 40 + acol));
            }
            const int krow = kk + (lane & 7) + ((lane >> 3) & 1) * 8;
#pragma unroll
            for (int ntp = 0; ntp < 4; ntp++) {
                const int ncol = wn + ntp * 16 + ((lane >> 4) << 3);
                unsigned bh[4];
                ldm_x4_t(bh, s2u(s + 10240 + krow * 136 + ncol));
#pragma unroll
                for (int mt = 0; mt < 2; mt++) {
                    mma_f16(d[mt][2 * ntp],     ah[mt], bh);
                    mma_f16(d[mt][2 * ntp],     al[mt], bh);
                    mma_f16(d[mt][2 * ntp + 1], ah[mt], bh + 2);
                    mma_f16(d[mt][2 * ntp + 1], al[mt], bh + 2);
                }
            }
        }
        __syncthreads();
    }

    // epilogue (per segment)
#pragma unroll
    for (int mt = 0; mt < 2; mt++) {
        int r0 = bm * 128 + wm + mt * 16 + g;
#pragma unroll
        for (int nt = 0; nt < 8; nt++) {
            int c = bnn * 128 + wn + nt * 8 + 2 * tg;
            float v0 = d[mt][nt][0] * alpha, v1 = d[mt][nt][1] * alpha;
            float v2 = d[mt][nt][2] * alpha, v3 = d[mt][nt][3] * alpha;
            if (seg == 0) {
                *(unsigned*)(Q_ + (size_t)r0 * NQK + c)       = packh2(v0, v1);
                *(unsigned*)(Q_ + (size_t)(r0 + 8) * NQK + c) = packh2(v2, v3);
            } else if (seg == 1) {
                unsigned h01, l01, h23, l23;
                split2h(v0, v1, h01, l01);
                split2h(v2, v3, h23, l23);
                *(unsigned*)(Kh_ + (size_t)r0 * NQK + c)       = h01;
                *(unsigned*)(Kl_ + (size_t)r0 * NQK + c)       = l01;
                *(unsigned*)(Kh_ + (size_t)(r0 + 8) * NQK + c) = h23;
                *(unsigned*)(Kl_ + (size_t)(r0 + 8) * NQK + c) = l23;
            } else {
                *(unsigned*)(V_ + (size_t)r0 * NV + c)       = packh2(v0, v1);
                *(unsigned*)(V_ + (size_t)(r0 + 8) * NV + c) = packh2(v2, v3);
            }
        }
    }
}

// ---------------------------------------------------------------------------
// Flash attention (fp16): Q tile 128 (8 warps x m16), KV tile 64, 2-stage KV.
// S = Q*(Kh+Kl): 2 fp16 mmas.  P@V: single fp16 mma (k16).
// Smem bytes: Qs 18432 | Ps 18432 | stage0 44032 | stage1 44032 = 124928
//   stage: Kh[64][72] 9216 | Kl[64][72] 9216 | Vs[64][200] fp16 25600
// ---------------------------------------------------------------------------
#define FLASH_STAGE_BYTES 44032
#define FLASH_SMEM_BYTES  124928

__global__ __launch_bounds__(256, 1)
void flash_tc(const __half* __restrict__ Qg, const __half* __restrict__ Khg,
              const __half* __restrict__ Klg, const __half* __restrict__ V,
              float* __restrict__ out)
{
    extern __shared__ char smc[];
    __half* Qs = (__half*)smc;                     // [128][72]
    __half* Ps = (__half*)(smc + 18432);           // [128][72]

    const int tid = threadIdx.x, lane = tid & 31, wid = tid >> 5;
    const int g = lane >> 2, tg = lane & 3;
    const int w16 = wid * 16;
    const int b = blockIdx.y >> 3, h = blockIdx.y & 7;
    const int q0 = blockIdx.x * 128;
    const int NT = SEQ / 64;

    // Q tile (single fp16): 128 rows x 8 chunks of 8 halfs
#pragma unroll
    for (int r = 0; r < 4; r++) {
        int idx = tid + r * 256;
        int qr = idx >> 3, kc = (idx & 7) << 3;
        *(uint4*)(Qs + qr * 72 + kc) =
            *(const uint4*)(Qg + (size_t)(b * SEQ + q0 + qr) * NQK + h * DK + kc);
    }

    auto issue_kv = [&](int kt) {
        char* st = smc + 36864 + (kt & 1) * FLASH_STAGE_BYTES;
        const int kv0 = kt * 64;
#pragma unroll
        for (int i = 0; i < 2; i++) {            // K hi/lo: 64 rows x 8 chunks each
            int idx = tid + i * 256;
            int r = idx >> 3, q = idx & 7;
            size_t go = (size_t)(b * SEQ + kv0 + r) * NQK + h * DK + q * 8;
            cp16(st + r * 144 + q * 16, Khg + go);
            cp16(st + 9216 + r * 144 + q * 16, Klg + go);
        }
#pragma unroll
        for (int i = 0; i < 6; i++) {            // V: 64 rows x 24 chunks of 8 halfs
            int idx = tid + i * 256;
            int r = idx / 24, cq = idx % 24;
            cp16(st + 18432 + r * 400 + cq * 16,
                 V + (size_t)(b * SEQ + kv0 + r) * NV + h * DV + cq * 8);
        }
        cp_commit();
    };

    float m0 = -1e30f, m1 = -1e30f, l0s = 0.f, l1s = 0.f;
    float o[24][4];
#pragma unroll
    for (int nt = 0; nt < 24; nt++)
#pragma unroll
        for (int i = 0; i < 4; i++) o[nt][i] = 0.f;

    issue_kv(0);
    for (int kt = 0; kt < NT; kt++) {
        if (kt + 1 < NT) { issue_kv(kt + 1); cp_wait1(); }
        else             { cp_wait0(); }
        __syncthreads();

        char* st = smc + 36864 + (kt & 1) * FLASH_STAGE_BYTES;
        __half* Kh_s = (__half*)st;
        __half* Kl_s = (__half*)(st + 9216);
        __half* Vs   = (__half*)(st + 18432);

        // ---- S = Q @ (Kh + Kl)^T : 2 fp16 mmas per 16x16 K-chunk ----
        float s[8][4];
#pragma unroll
        for (int nt = 0; nt < 8; nt++)
#pragma unroll
            for (int i = 0; i < 4; i++) s[nt][i] = 0.f;

#pragma unroll
        for (int ks = 0; ks < 4; ks++) {
            const int kk = ks * 16;
            unsigned q[4];
            const int arow = lane & 15, acol = kk + ((lane >> 4) << 3);
            ldm_x4(q, s2u(Qs + (w16 + arow) * 72 + acol));
            const int nrow = ((lane >> 4) << 3) + (lane & 7);
            const int kcol = kk + ((lane >> 3) & 1) * 8;
#pragma unroll
            for (int ntp = 0; ntp < 4; ntp++) {
                unsigned kh[4], kl[4];
                ldm_x4(kh, s2u(Kh_s + (ntp * 16 + nrow) * 72 + kcol));
                ldm_x4(kl, s2u(Kl_s + (ntp * 16 + nrow) * 72 + kcol));
                mma_f16(s[2 * ntp],     q, kh);
                mma_f16(s[2 * ntp],     q, kl);
                mma_f16(s[2 * ntp + 1], q, kh + 2);
                mma_f16(s[2 * ntp + 1], q, kl + 2);
            }
        }

        // ---- online softmax ----
        float mx0 = -1e30f, mx1 = -1e30f;
#pragma unroll
        for (int nt = 0; nt < 8; nt++) {
            mx0 = fmaxf(mx0, fmaxf(s[nt][0], s[nt][1]));
            mx1 = fmaxf(mx1, fmaxf(s[nt][2], s[nt][3]));
        }
        mx0 = fmaxf(mx0, __shfl_xor_sync(0xffffffffu, mx0, 1));
        mx0 = fmaxf(mx0, __shfl_xor_sync(0xffffffffu, mx0, 2));
        mx1 = fmaxf(mx1, __shfl_xor_sync(0xffffffffu, mx1, 1));
        mx1 = fmaxf(mx1, __shfl_xor_sync(0xffffffffu, mx1, 2));

        float nm0 = fmaxf(m0, mx0), nm1 = fmaxf(m1, mx1);
        float a0 = __expf(m0 - nm0), a1 = __expf(m1 - nm1);
        float sum0 = 0.f, sum1 = 0.f;
#pragma unroll
        for (int nt = 0; nt < 8; nt++) {
            s[nt][0] = __expf(s[nt][0] - nm0); sum0 += s[nt][0];
            s[nt][1] = __expf(s[nt][1] - nm0); sum0 += s[nt][1];
            s[nt][2] = __expf(s[nt][2] - nm1); sum1 += s[nt][2];
            s[nt][3] = __expf(s[nt][3] - nm1); sum1 += s[nt][3];
        }
        sum0 += __shfl_xor_sync(0xffffffffu, sum0, 1);
        sum0 += __shfl_xor_sync(0xffffffffu, sum0, 2);
        sum1 += __shfl_xor_sync(0xffffffffu, sum1, 1);
        sum1 += __shfl_xor_sync(0xffffffffu, sum1, 2);
        l0s = l0s * a0 + sum0;  l1s = l1s * a1 + sum1;
        m0 = nm0;  m1 = nm1;

#pragma unroll
        for (int nt = 0; nt < 24; nt++) {
            o[nt][0] *= a0; o[nt][1] *= a0;
            o[nt][2] *= a1; o[nt][3] *= a1;
        }
        // store P as fp16
#pragma unroll
        for (int nt = 0; nt < 8; nt++) {
            *(unsigned*)(Ps + (w16 + g) * 72 + nt * 8 + 2 * tg)     = packh2(s[nt][0], s[nt][1]);
            *(unsigned*)(Ps + (w16 + g + 8) * 72 + nt * 8 + 2 * tg) = packh2(s[nt][2], s[nt][3]);
        }
        __syncwarp();

        // ---- O += P @ V (single fp16 mma, k16) ----
#pragma unroll
        for (int ks = 0; ks < 4; ks++) {
            const int kk = ks * 16;
            unsigned ap[4];
            const int arow = lane & 15, acol = kk + ((lane >> 4) << 3);
            ldm_x4(ap, s2u(Ps + (w16 + arow) * 72 + acol));
            const int krow = kk + (lane & 7) + ((lane >> 3) & 1) * 8;
#pragma unroll
            for (int ntp = 0; ntp < 12; ntp++) {
                const int ncol = ntp * 16 + ((lane >> 4) << 3);
                unsigned bv[4];
                ldm_x4_t(bv, s2u(Vs + krow * 200 + ncol));
                mma_f16(o[2 * ntp],     ap, bv);
                mma_f16(o[2 * ntp + 1], ap, bv + 2);
            }
        }
        __syncthreads();   // protect stage buffer before next issue overwrites
    }

    // epilogue
    float i0 = 1.f / l0s, i1 = 1.f / l1s;
    int r0 = b * SEQ + q0 + w16 + g, r1 = r0 + 8;
#pragma unroll
    for (int nt = 0; nt < 24; nt++) {
        int c = h * DV + nt * 8 + 2 * tg;
        *(float2*)(out + (size_t)r0 * NV + c) = make_float2(o[nt][0] * i0, o[nt][1] * i0);
        *(float2*)(out + (size_t)r1 * NV + c) = make_float2(o[nt][2] * i1, o[nt][3] * i1);
    }
}

// ---------------------------------------------------------------------------
extern "C" void kernel_launch(void* const* d_in, const int* in_sizes, int n_in,
                              void* d_out, int out_size)
{
    const float* X  = (const float*)d_in[0];
    const float* Wq = (const float*)d_in[1];
    const float* Wk = (const float*)d_in[2];
    const float* Wv = (const float*)d_in[3];
    float* out = (float*)d_out;

    void *xh, *xl, *wq, *wk, *wv, *q, *kh, *kl, *pv;
    cudaGetSymbolAddress(&xh, g_Xh); cudaGetSymbolAddress(&xl, g_Xl);
    cudaGetSymbolAddress(&wq, g_Wq); cudaGetSymbolAddress(&wk, g_Wk);
    cudaGetSymbolAddress(&wv, g_Wv);
    cudaGetSymbolAddress(&q, g_Q);
    cudaGetSymbolAddress(&kh, g_Kh); cudaGetSymbolAddress(&kl, g_Kl);
    cudaGetSymbolAddress(&pv, g_V);

    static bool attr_set = false;
    if (!attr_set) {
        cudaFuncSetAttribute(gemm_fused,
            cudaFuncAttributeMaxDynamicSharedMemorySize, GEMM_SMEM_BYTES);
        cudaFuncSetAttribute(flash_tc,
            cudaFuncAttributeMaxDynamicSharedMemorySize, FLASH_SMEM_BYTES);
        attr_set = true;
    }

    // X -> fp16 hi/lo ; W -> fp16 single
    convert_split_h<<<(MROWS * DMODEL / 4 + 255) / 256, 256>>>(
        (const float4*)X, (uint2*)xh, (uint2*)xl, MROWS * DMODEL / 4);
    convert_h<<<(DMODEL * NQK / 4 + 255) / 256, 256>>>(
        (const float4*)Wq, (uint2*)wq, DMODEL * NQK / 4);
    convert_h<<<(DMODEL * NQK / 4 + 255) / 256, 256>>>(
        (const float4*)Wk, (uint2*)wk, DMODEL * NQK / 4);
    convert_h<<<(DMODEL * NV / 4 + 255) / 256, 256>>>(
        (const float4*)Wv, (uint2*)wv, DMODEL * NV / 4);

    // one fused projection GEMM: Q | K | V
    gemm_fused<<<dim3(20, MROWS / 128), 256, GEMM_SMEM_BYTES>>>(
        (const __half*)xh, (const __half*)xl,
        (const __half*)wq, (const __half*)wk, (const __half*)wv,
        (__half*)q, (__half*)kh, (__half*)kl, (__half*)pv);

    flash_tc<<<dim3(SEQ / 128, BATCH * HEADS), 256, FLASH_SMEM_BYTES>>>(
        (const __half*)q, (const __half*)kh, (const __half*)kl,
        (const __half*)pv, out);
}

// round 8
// speedup vs baseline: 5.1753x; 1.0643x over previous
#include <cuda_runtime.h>
#include <cuda_fp16.h>
#include <cstdint>

#define HEADS   8
#define DK      64
#define DV      192
#define BATCH   4
#define SEQ     1536
#define DMODEL  1536
#define MROWS   (BATCH*SEQ)          // 6144
#define NQK     (HEADS*DK)           // 512
#define NV      (HEADS*DV)           // 1536

// ------------------------- global scratch (no allocs) -----------------------
__device__ __half g_Xh[MROWS * DMODEL], g_Xl[MROWS * DMODEL];   // X hi/lo fp16
__device__ __half g_Wq[DMODEL * NQK];                            // W single fp16
__device__ __half g_Wk[DMODEL * NQK];
__device__ __half g_Wv[DMODEL * NV];
__device__ __half g_Q [MROWS * NQK];                             // Q single fp16 (pre-scaled)
__device__ __half g_Kh[MROWS * NQK], g_Kl[MROWS * NQK];          // K hi/lo fp16
__device__ __half g_V [MROWS * NV];                              // V single fp16

// ------------------------------- helpers ------------------------------------
__device__ __forceinline__ unsigned s2u(const void* p) {
    return (unsigned)__cvta_generic_to_shared(p);
}
__device__ __forceinline__ unsigned packh2(float a, float b) {
    __half ha = __float2half_rn(a), hb = __float2half_rn(b);
    return (unsigned)__half_as_ushort(ha) | ((unsigned)__half_as_ushort(hb) << 16);
}
__device__ __forceinline__ void split2h(float x, float y, unsigned& h, unsigned& l) {
    __half hx = __float2half_rn(x), hy = __float2half_rn(y);
    __half lx = __float2half_rn(x - __half2float(hx));
    __half ly = __float2half_rn(y - __half2float(hy));
    h = (unsigned)__half_as_ushort(hx) | ((unsigned)__half_as_ushort(hy) << 16);
    l = (unsigned)__half_as_ushort(lx) | ((unsigned)__half_as_ushort(ly) << 16);
}
__device__ __forceinline__ void ldm_x4(unsigned* r, unsigned a) {
    asm volatile("ldmatrix.sync.aligned.m8n8.x4.shared.b16 {%0,%1,%2,%3}, [%4];"
        : "=r"(r[0]), "=r"(r[1]), "=r"(r[2]), "=r"(r[3]) : "r"(a));
}
__device__ __forceinline__ void ldm_x4_t(unsigned* r, unsigned a) {
    asm volatile("ldmatrix.sync.aligned.m8n8.x4.trans.shared.b16 {%0,%1,%2,%3}, [%4];"
        : "=r"(r[0]), "=r"(r[1]), "=r"(r[2]), "=r"(r[3]) : "r"(a));
}
__device__ __forceinline__ void mma_f16(float* d, const unsigned* a, const unsigned* b) {
    asm volatile(
        "mma.sync.aligned.m16n8k16.row.col.f32.f16.f16.f32 "
        "{%0,%1,%2,%3}, {%4,%5,%6,%7}, {%8,%9}, {%0,%1,%2,%3};\n"
        : "+f"(d[0]), "+f"(d[1]), "+f"(d[2]), "+f"(d[3])
        : "r"(a[0]), "r"(a[1]), "r"(a[2]), "r"(a[3]), "r"(b[0]), "r"(b[1]));
}
__device__ __forceinline__ void cp16(void* dst, const void* src) {
    unsigned d = s2u(dst);
    asm volatile("cp.async.ca.shared.global [%0], [%1], 16;\n" :: "r"(d), "l"(src));
}
__device__ __forceinline__ void cp_commit() { asm volatile("cp.async.commit_group;\n"); }
__device__ __forceinline__ void cp_wait0()  { asm volatile("cp.async.wait_group 0;\n" ::: "memory"); }
__device__ __forceinline__ void cp_wait1()  { asm volatile("cp.async.wait_group 1;\n" ::: "memory"); }

// --------------------- fp32 -> fp16 hi/lo split (X) --------------------------
__global__ void convert_split_h(const float4* __restrict__ in,
                                uint2* __restrict__ oh, uint2* __restrict__ ol, int n4)
{
    int i = blockIdx.x * blockDim.x + threadIdx.x;
    if (i >= n4) return;
    float4 v = in[i];
    uint2 H, L;
    split2h(v.x, v.y, H.x, L.x);
    split2h(v.z, v.w, H.y, L.y);
    oh[i] = H;  ol[i] = L;
}
// --------------------- fp32 -> fp16 single convert (W) -----------------------
__global__ void convert_h(const float4* __restrict__ in, uint2* __restrict__ o, int n4)
{
    int i = blockIdx.x * blockDim.x + threadIdx.x;
    if (i >= n4) return;
    float4 v = in[i];
    uint2 H;
    H.x = packh2(v.x, v.y);
    H.y = packh2(v.z, v.w);
    o[i] = H;
}

// ---------------------------------------------------------------------------
// Fused projection GEMM (fp16, 2-product): one kernel computes Q, K, V.
// C = alpha * (Xh + Xl) @ W.  Segments: bn<4 -> Q ; bn<8 -> K ; else -> V.
// BM=128 BN=128 BK=32, 256 thr, warp tile 32x64. cp.async 3-stage, 1 sync/iter.
// Smem/stage (halfs): Ah[128][40] | Al[128][40] | B[32][136] = 14592 (29184 B)
// ---------------------------------------------------------------------------
#define GEMM_STAGE_ELEMS 14592
#define GEMM_SMEM_BYTES  (3 * GEMM_STAGE_ELEMS * 2)   // 87552

__global__ __launch_bounds__(256, 2)
void gemm_fused(const __half* __restrict__ Ahg, const __half* __restrict__ Alg,
                const __half* __restrict__ Wq_, const __half* __restrict__ Wk_,
                const __half* __restrict__ Wv_,
                __half* __restrict__ Q_, __half* __restrict__ Kh_,
                __half* __restrict__ Kl_, __half* __restrict__ V_)
{
    extern __shared__ __half smg[];
    const int tid = threadIdx.x, lane = tid & 31, wid = tid >> 5;
    const int g = lane >> 2, tg = lane & 3;
    const int wm = (wid >> 1) * 32, wn = (wid & 1) * 64;
    const int bm = blockIdx.y, bn_g = blockIdx.x;
    const int K = DMODEL;
    const int NT = K >> 5;   // 48

    const __half* Bg;
    int Nb, bnn, seg;
    if (bn_g < 4)      { Bg = Wq_; Nb = NQK; bnn = bn_g;     seg = 0; }
    else if (bn_g < 8) { Bg = Wk_; Nb = NQK; bnn = bn_g - 4; seg = 1; }
    else               { Bg = Wv_; Nb = NV;  bnn = bn_g - 8; seg = 2; }
    const float alpha = (seg == 0) ? 0.125f : 1.0f;

    float d[2][8][4];
#pragma unroll
    for (int mt = 0; mt < 2; mt++)
#pragma unroll
        for (int nt = 0; nt < 8; nt++)
#pragma unroll
            for (int i = 0; i < 4; i++) d[mt][nt][i] = 0.f;

    auto issue = [&](int it) {
        __half* s = smg + (it % 3) * GEMM_STAGE_ELEMS;
        int k0 = it * 32;
#pragma unroll
        for (int j = 0; j < 2; j++) {
            int c = tid + j * 256;
            int ar = c >> 2, ac = (c & 3) << 3;
            size_t ga = (size_t)(bm * 128 + ar) * K + k0 + ac;
            cp16(s + ar * 40 + ac,        Ahg + ga);
            cp16(s + 5120 + ar * 40 + ac, Alg + ga);
            int br = c >> 4, bc = (c & 15) << 3;
            size_t gb = (size_t)(k0 + br) * Nb + bnn * 128 + bc;
            cp16(s + 10240 + br * 136 + bc, Bg + gb);
        }
        cp_commit();
    };

    issue(0);
    issue(1);
    for (int it = 0; it < NT; it++) {
        if (it + 1 < NT) cp_wait1(); else cp_wait0();
        __syncthreads();
        if (it + 2 < NT) issue(it + 2);
        const __half* s = smg + (it % 3) * GEMM_STAGE_ELEMS;

#pragma unroll
        for (int ks = 0; ks < 2; ks++) {
            const int kk = ks * 16;
            unsigned ah[2][4], al[2][4];
            const int arow = lane & 15, acol = kk + ((lane >> 4) << 3);
#pragma unroll
            for (int mt = 0; mt < 2; mt++) {
                ldm_x4(ah[mt], s2u(s + (wm + mt * 16 + arow) * 40 + acol));
                ldm_x4(al[mt], s2u(s + 5120 + (wm + mt * 16 + arow) * 40 + acol));
            }
            const int krow = kk + (lane & 7) + ((lane >> 3) & 1) * 8;
#pragma unroll
            for (int ntp = 0; ntp < 4; ntp++) {
                const int ncol = wn + ntp * 16 + ((lane >> 4) << 3);
                unsigned bh[4];
                ldm_x4_t(bh, s2u(s + 10240 + krow * 136 + ncol));
#pragma unroll
                for (int mt = 0; mt < 2; mt++) {
                    mma_f16(d[mt][2 * ntp],     ah[mt], bh);
                    mma_f16(d[mt][2 * ntp],     al[mt], bh);
                    mma_f16(d[mt][2 * ntp + 1], ah[mt], bh + 2);
                    mma_f16(d[mt][2 * ntp + 1], al[mt], bh + 2);
                }
            }
        }
    }

    // epilogue (per segment)
#pragma unroll
    for (int mt = 0; mt < 2; mt++) {
        int r0 = bm * 128 + wm + mt * 16 + g;
#pragma unroll
        for (int nt = 0; nt < 8; nt++) {
            int c = bnn * 128 + wn + nt * 8 + 2 * tg;
            float v0 = d[mt][nt][0] * alpha, v1 = d[mt][nt][1] * alpha;
            float v2 = d[mt][nt][2] * alpha, v3 = d[mt][nt][3] * alpha;
            if (seg == 0) {
                *(unsigned*)(Q_ + (size_t)r0 * NQK + c)       = packh2(v0, v1);
                *(unsigned*)(Q_ + (size_t)(r0 + 8) * NQK + c) = packh2(v2, v3);
            } else if (seg == 1) {
                unsigned h01, l01, h23, l23;
                split2h(v0, v1, h01, l01);
                split2h(v2, v3, h23, l23);
                *(unsigned*)(Kh_ + (size_t)r0 * NQK + c)       = h01;
                *(unsigned*)(Kl_ + (size_t)r0 * NQK + c)       = l01;
                *(unsigned*)(Kh_ + (size_t)(r0 + 8) * NQK + c) = h23;
                *(unsigned*)(Kl_ + (size_t)(r0 + 8) * NQK + c) = l23;
            } else {
                *(unsigned*)(V_ + (size_t)r0 * NV + c)       = packh2(v0, v1);
                *(unsigned*)(V_ + (size_t)(r0 + 8) * NV + c) = packh2(v2, v3);
            }
        }
    }
}

// ---------------------------------------------------------------------------
// Flash attention (fp16): Q tile 128 (8 warps x m16), KV tile 64, 3-stage KV.
// S = Q*(Kh+Kl): 2 fp16 mmas.  P@V from REGISTERS (S C-frag == PV A-frag).
// Q fragments hoisted out of KV loop. One __syncthreads per iteration.
// Smem bytes: Qs 18432 | stage x3 44032 = 150528
//   stage: Kh[64][72] 9216 | Kl[64][72] 9216 | Vs[64][200] fp16 25600
// ---------------------------------------------------------------------------
#define FLASH_STAGE_BYTES 44032
#define FLASH_SMEM_BYTES  (18432 + 3 * FLASH_STAGE_BYTES)   // 150528

__global__ __launch_bounds__(256, 1)
void flash_tc(const __half* __restrict__ Qg, const __half* __restrict__ Khg,
              const __half* __restrict__ Klg, const __half* __restrict__ V,
              float* __restrict__ out)
{
    extern __shared__ char smc[];
    __half* Qs = (__half*)smc;                     // [128][72]

    const int tid = threadIdx.x, lane = tid & 31, wid = tid >> 5;
    const int g = lane >> 2, tg = lane & 3;
    const int w16 = wid * 16;
    const int b = blockIdx.y >> 3, h = blockIdx.y & 7;
    const int q0 = blockIdx.x * 128;
    const int NT = SEQ / 64;   // 24

    // Q tile (single fp16)
#pragma unroll
    for (int r = 0; r < 4; r++) {
        int idx = tid + r * 256;
        int qr = idx >> 3, kc = (idx & 7) << 3;
        *(uint4*)(Qs + qr * 72 + kc) =
            *(const uint4*)(Qg + (size_t)(b * SEQ + q0 + qr) * NQK + h * DK + kc);
    }

    auto issue_kv = [&](int kt) {
        char* st = smc + 18432 + (kt % 3) * FLASH_STAGE_BYTES;
        const int kv0 = kt * 64;
#pragma unroll
        for (int i = 0; i < 2; i++) {            // K hi/lo: 64 rows x 8 chunks each
            int idx = tid + i * 256;
            int r = idx >> 3, q = idx & 7;
            size_t go = (size_t)(b * SEQ + kv0 + r) * NQK + h * DK + q * 8;
            cp16(st + r * 144 + q * 16, Khg + go);
            cp16(st + 9216 + r * 144 + q * 16, Klg + go);
        }
#pragma unroll
        for (int i = 0; i < 6; i++) {            // V: 64 rows x 24 chunks of 8 halfs
            int idx = tid + i * 256;
            int r = idx / 24, cq = idx % 24;
            cp16(st + 18432 + r * 400 + cq * 16,
                 V + (size_t)(b * SEQ + kv0 + r) * NV + h * DV + cq * 8);
        }
        cp_commit();
    };

    issue_kv(0);
    issue_kv(1);
    __syncthreads();   // Qs visible to all warps

    // Hoist Q fragments (loop-invariant)
    unsigned qf[4][4];
#pragma unroll
    for (int ks = 0; ks < 4; ks++) {
        const int arow = lane & 15, acol = ks * 16 + ((lane >> 4) << 3);
        ldm_x4(qf[ks], s2u(Qs + (w16 + arow) * 72 + acol));
    }

    float m0 = -1e30f, m1 = -1e30f, l0s = 0.f, l1s = 0.f;
    float o[24][4];
#pragma unroll
    for (int nt = 0; nt < 24; nt++)
#pragma unroll
        for (int i = 0; i < 4; i++) o[nt][i] = 0.f;

    for (int kt = 0; kt < NT; kt++) {
        if (kt + 1 < NT) cp_wait1(); else cp_wait0();
        __syncthreads();
        if (kt + 2 < NT) issue_kv(kt + 2);

        char* st = smc + 18432 + (kt % 3) * FLASH_STAGE_BYTES;
        __half* Kh_s = (__half*)st;
        __half* Kl_s = (__half*)(st + 9216);
        __half* Vs   = (__half*)(st + 18432);

        // ---- S = Q @ (Kh + Kl)^T ----
        float s[8][4];
#pragma unroll
        for (int nt = 0; nt < 8; nt++)
#pragma unroll
            for (int i = 0; i < 4; i++) s[nt][i] = 0.f;

#pragma unroll
        for (int ks = 0; ks < 4; ks++) {
            const int kk = ks * 16;
            const int nrow = ((lane >> 4) << 3) + (lane & 7);
            const int kcol = kk + ((lane >> 3) & 1) * 8;
#pragma unroll
            for (int ntp = 0; ntp < 4; ntp++) {
                unsigned kh[4], kl[4];
                ldm_x4(kh, s2u(Kh_s + (ntp * 16 + nrow) * 72 + kcol));
                ldm_x4(kl, s2u(Kl_s + (ntp * 16 + nrow) * 72 + kcol));
                mma_f16(s[2 * ntp],     qf[ks], kh);
                mma_f16(s[2 * ntp],     qf[ks], kl);
                mma_f16(s[2 * ntp + 1], qf[ks], kh + 2);
                mma_f16(s[2 * ntp + 1], qf[ks], kl + 2);
            }
        }

        // ---- online softmax ----
        float mx0 = -1e30f, mx1 = -1e30f;
#pragma unroll
        for (int nt = 0; nt < 8; nt++) {
            mx0 = fmaxf(mx0, fmaxf(s[nt][0], s[nt][1]));
            mx1 = fmaxf(mx1, fmaxf(s[nt][2], s[nt][3]));
        }
        mx0 = fmaxf(mx0, __shfl_xor_sync(0xffffffffu, mx0, 1));
        mx0 = fmaxf(mx0, __shfl_xor_sync(0xffffffffu, mx0, 2));
        mx1 = fmaxf(mx1, __shfl_xor_sync(0xffffffffu, mx1, 1));
        mx1 = fmaxf(mx1, __shfl_xor_sync(0xffffffffu, mx1, 2));

        float nm0 = fmaxf(m0, mx0), nm1 = fmaxf(m1, mx1);
        float a0 = __expf(m0 - nm0), a1 = __expf(m1 - nm1);
        float sum0 = 0.f, sum1 = 0.f;
#pragma unroll
        for (int nt = 0; nt < 8; nt++) {
            s[nt][0] = __expf(s[nt][0] - nm0); sum0 += s[nt][0];
            s[nt][1] = __expf(s[nt][1] - nm0); sum0 += s[nt][1];
            s[nt][2] = __expf(s[nt][2] - nm1); sum1 += s[nt][2];
            s[nt][3] = __expf(s[nt][3] - nm1); sum1 += s[nt][3];
        }
        sum0 += __shfl_xor_sync(0xffffffffu, sum0, 1);
        sum0 += __shfl_xor_sync(0xffffffffu, sum0, 2);
        sum1 += __shfl_xor_sync(0xffffffffu, sum1, 1);
        sum1 += __shfl_xor_sync(0xffffffffu, sum1, 2);
        l0s = l0s * a0 + sum0;  l1s = l1s * a1 + sum1;
        m0 = nm0;  m1 = nm1;

#pragma unroll
        for (int nt = 0; nt < 24; nt++) {
            o[nt][0] *= a0; o[nt][1] *= a0;
            o[nt][2] *= a1; o[nt][3] *= a1;
        }

        // ---- O += P @ V, P fragments built directly from S registers ----
#pragma unroll
        for (int c = 0; c < 4; c++) {
            unsigned ap[4];
            ap[0] = packh2(s[2 * c][0],     s[2 * c][1]);
            ap[1] = packh2(s[2 * c][2],     s[2 * c][3]);
            ap[2] = packh2(s[2 * c + 1][0], s[2 * c + 1][1]);
            ap[3] = packh2(s[2 * c + 1][2], s[2 * c + 1][3]);
            const int krow = 16 * c + (lane & 7) + ((lane >> 3) & 1) * 8;
#pragma unroll
            for (int ntp = 0; ntp < 12; ntp++) {
                const int ncol = ntp * 16 + ((lane >> 4) << 3);
                unsigned bv[4];
                ldm_x4_t(bv, s2u(Vs + krow * 200 + ncol));
                mma_f16(o[2 * ntp],     ap, bv);
                mma_f16(o[2 * ntp + 1], ap, bv + 2);
            }
        }
    }

    // epilogue
    float i0 = 1.f / l0s, i1 = 1.f / l1s;
    int r0 = b * SEQ + q0 + w16 + g, r1 = r0 + 8;
#pragma unroll
    for (int nt = 0; nt < 24; nt++) {
        int c = h * DV + nt * 8 + 2 * tg;
        *(float2*)(out + (size_t)r0 * NV + c) = make_float2(o[nt][0] * i0, o[nt][1] * i0);
        *(float2*)(out + (size_t)r1 * NV + c) = make_float2(o[nt][2] * i1, o[nt][3] * i1);
    }
}

// ---------------------------------------------------------------------------
extern "C" void kernel_launch(void* const* d_in, const int* in_sizes, int n_in,
                              void* d_out, int out_size)
{
    const float* X  = (const float*)d_in[0];
    const float* Wq = (const float*)d_in[1];
    const float* Wk = (const float*)d_in[2];
    const float* Wv = (const float*)d_in[3];
    float* out = (float*)d_out;

    void *xh, *xl, *wq, *wk, *wv, *q, *kh, *kl, *pv;
    cudaGetSymbolAddress(&xh, g_Xh); cudaGetSymbolAddress(&xl, g_Xl);
    cudaGetSymbolAddress(&wq, g_Wq); cudaGetSymbolAddress(&wk, g_Wk);
    cudaGetSymbolAddress(&wv, g_Wv);
    cudaGetSymbolAddress(&q, g_Q);
    cudaGetSymbolAddress(&kh, g_Kh); cudaGetSymbolAddress(&kl, g_Kl);
    cudaGetSymbolAddress(&pv, g_V);

    static bool attr_set = false;
    if (!attr_set) {
        cudaFuncSetAttribute(gemm_fused,
            cudaFuncAttributeMaxDynamicSharedMemorySize, GEMM_SMEM_BYTES);
        cudaFuncSetAttribute(flash_tc,
            cudaFuncAttributeMaxDynamicSharedMemorySize, FLASH_SMEM_BYTES);
        attr_set = true;
    }

    // X -> fp16 hi/lo ; W -> fp16 single
    convert_split_h<<<(MROWS * DMODEL / 4 + 255) / 256, 256>>>(
        (const float4*)X, (uint2*)xh, (uint2*)xl, MROWS * DMODEL / 4);
    convert_h<<<(DMODEL * NQK / 4 + 255) / 256, 256>>>(
        (const float4*)Wq, (uint2*)wq, DMODEL * NQK / 4);
    convert_h<<<(DMODEL * NQK / 4 + 255) / 256, 256>>>(
        (const float4*)Wk, (uint2*)wk, DMODEL * NQK / 4);
    convert_h<<<(DMODEL * NV / 4 + 255) / 256, 256>>>(
        (const float4*)Wv, (uint2*)wv, DMODEL * NV / 4);

    // one fused projection GEMM: Q | K | V
    gemm_fused<<<dim3(20, MROWS / 128), 256, GEMM_SMEM_BYTES>>>(
        (const __half*)xh, (const __half*)xl,
        (const __half*)wq, (const __half*)wk, (const __half*)wv,
        (__half*)q, (__half*)kh, (__half*)kl, (__half*)pv);

    flash_tc<<<dim3(SEQ / 128, BATCH * HEADS), 256, FLASH_SMEM_BYTES>>>(
        (const __half*)q, (const __half*)kh, (const __half*)kl,
        (const __half*)pv, out);
}

// round 9
// speedup vs baseline: 5.3827x; 1.0401x over previous
#include <cuda_runtime.h>
#include <cuda_fp16.h>
#include <cstdint>

#define HEADS   8
#define DK      64
#define DV      192
#define BATCH   4
#define SEQ     1536
#define DMODEL  1536
#define MROWS   (BATCH*SEQ)          // 6144
#define NQK     (HEADS*DK)           // 512
#define NV      (HEADS*DV)           // 1536

// ------------------------- global scratch (no allocs) -----------------------
__device__ __half g_Xh[MROWS * DMODEL], g_Xl[MROWS * DMODEL];   // X hi/lo fp16
__device__ __half g_Wq[DMODEL * NQK];                            // W single fp16
__device__ __half g_Wk[DMODEL * NQK];
__device__ __half g_Wv[DMODEL * NV];
__device__ __half g_Q [MROWS * NQK];                             // Q single fp16 (pre-scaled)
__device__ __half g_Kh[MROWS * NQK], g_Kl[MROWS * NQK];          // K hi/lo fp16
__device__ __half g_V [MROWS * NV];                              // V single fp16

// ------------------------------- helpers ------------------------------------
__device__ __forceinline__ unsigned s2u(const void* p) {
    return (unsigned)__cvta_generic_to_shared(p);
}
__device__ __forceinline__ unsigned packh2(float a, float b) {
    __half ha = __float2half_rn(a), hb = __float2half_rn(b);
    return (unsigned)__half_as_ushort(ha) | ((unsigned)__half_as_ushort(hb) << 16);
}
__device__ __forceinline__ void split2h(float x, float y, unsigned& h, unsigned& l) {
    __half hx = __float2half_rn(x), hy = __float2half_rn(y);
    __half lx = __float2half_rn(x - __half2float(hx));
    __half ly = __float2half_rn(y - __half2float(hy));
    h = (unsigned)__half_as_ushort(hx) | ((unsigned)__half_as_ushort(hy) << 16);
    l = (unsigned)__half_as_ushort(lx) | ((unsigned)__half_as_ushort(ly) << 16);
}
__device__ __forceinline__ void ldm_x4(unsigned* r, unsigned a) {
    asm volatile("ldmatrix.sync.aligned.m8n8.x4.shared.b16 {%0,%1,%2,%3}, [%4];"
        : "=r"(r[0]), "=r"(r[1]), "=r"(r[2]), "=r"(r[3]) : "r"(a));
}
__device__ __forceinline__ void ldm_x4_t(unsigned* r, unsigned a) {
    asm volatile("ldmatrix.sync.aligned.m8n8.x4.trans.shared.b16 {%0,%1,%2,%3}, [%4];"
        : "=r"(r[0]), "=r"(r[1]), "=r"(r[2]), "=r"(r[3]) : "r"(a));
}
__device__ __forceinline__ void mma_f16(float* d, const unsigned* a, const unsigned* b) {
    asm volatile(
        "mma.sync.aligned.m16n8k16.row.col.f32.f16.f16.f32 "
        "{%0,%1,%2,%3}, {%4,%5,%6,%7}, {%8,%9}, {%0,%1,%2,%3};\n"
        : "+f"(d[0]), "+f"(d[1]), "+f"(d[2]), "+f"(d[3])
        : "r"(a[0]), "r"(a[1]), "r"(a[2]), "r"(a[3]), "r"(b[0]), "r"(b[1]));
}
__device__ __forceinline__ void cp16(void* dst, const void* src) {
    unsigned d = s2u(dst);
    asm volatile("cp.async.ca.shared.global [%0], [%1], 16;\n" :: "r"(d), "l"(src));
}
__device__ __forceinline__ void cp_commit() { asm volatile("cp.async.commit_group;\n"); }
__device__ __forceinline__ void cp_wait0()  { asm volatile("cp.async.wait_group 0;\n" ::: "memory"); }
__device__ __forceinline__ void cp_wait1()  { asm volatile("cp.async.wait_group 1;\n" ::: "memory"); }

// --------------------- fp32 -> fp16 hi/lo split (X) --------------------------
__global__ void convert_split_h(const float4* __restrict__ in,
                                uint2* __restrict__ oh, uint2* __restrict__ ol, int n4)
{
    int i = blockIdx.x * blockDim.x + threadIdx.x;
    if (i >= n4) return;
    float4 v = in[i];
    uint2 H, L;
    split2h(v.x, v.y, H.x, L.x);
    split2h(v.z, v.w, H.y, L.y);
    oh[i] = H;  ol[i] = L;
}
// ----------- fp32 -> fp16 single convert, all three W in one launch ----------
#define NQK4 (DMODEL * NQK / 4)   // 196608
#define NV4  (DMODEL * NV / 4)    // 589824
__global__ void convert_w_all(const float4* __restrict__ wq, const float4* __restrict__ wk,
                              const float4* __restrict__ wv,
                              uint2* __restrict__ oq, uint2* __restrict__ ok,
                              uint2* __restrict__ ov)
{
    int i = blockIdx.x * blockDim.x + threadIdx.x;
    const float4* in;  uint2* o;  int j;
    if (i < NQK4)               { in = wq; o = oq; j = i; }
    else if (i < 2 * NQK4)      { in = wk; o = ok; j = i - NQK4; }
    else if (i < 2 * NQK4 + NV4){ in = wv; o = ov; j = i - 2 * NQK4; }
    else return;
    float4 v = in[j];
    uint2 H;
    H.x = packh2(v.x, v.y);
    H.y = packh2(v.z, v.w);
    o[j] = H;
}

// ---------------------------------------------------------------------------
// Fused projection GEMM (fp16): one kernel computes Q, K, V.
// Q,K: 2-product (Xh+Xl)@W.  V: 1-product Xh@W (V error unamplified at output).
// Segments: bn<4 -> Q ; bn<8 -> K ; else -> V.
// BM=128 BN=128 BK=32, 256 thr, warp tile 32x64. cp.async 3-stage, 1 sync/iter.
// Smem/stage (halfs): Ah[128][40] | Al[128][40] | B[32][136] = 14592 (29184 B)
// ---------------------------------------------------------------------------
#define GEMM_STAGE_ELEMS 14592
#define GEMM_SMEM_BYTES  (3 * GEMM_STAGE_ELEMS * 2)   // 87552

__global__ __launch_bounds__(256, 2)
void gemm_fused(const __half* __restrict__ Ahg, const __half* __restrict__ Alg,
                const __half* __restrict__ Wq_, const __half* __restrict__ Wk_,
                const __half* __restrict__ Wv_,
                __half* __restrict__ Q_, __half* __restrict__ Kh_,
                __half* __restrict__ Kl_, __half* __restrict__ V_)
{
    extern __shared__ __half smg[];
    const int tid = threadIdx.x, lane = tid & 31, wid = tid >> 5;
    const int g = lane >> 2, tg = lane & 3;
    const int wm = (wid >> 1) * 32, wn = (wid & 1) * 64;
    const int bm = blockIdx.y, bn_g = blockIdx.x;
    const int K = DMODEL;
    const int NT = K >> 5;   // 48

    const __half* Bg;
    int Nb, bnn, seg;
    if (bn_g < 4)      { Bg = Wq_; Nb = NQK; bnn = bn_g;     seg = 0; }
    else if (bn_g < 8) { Bg = Wk_; Nb = NQK; bnn = bn_g - 4; seg = 1; }
    else               { Bg = Wv_; Nb = NV;  bnn = bn_g - 8; seg = 2; }
    const float alpha = (seg == 0) ? 0.125f : 1.0f;
    const bool use_lo = (seg != 2);     // V: single product

    float d[2][8][4];
#pragma unroll
    for (int mt = 0; mt < 2; mt++)
#pragma unroll
        for (int nt = 0; nt < 8; nt++)
#pragma unroll
            for (int i = 0; i < 4; i++) d[mt][nt][i] = 0.f;

    auto issue = [&](int it) {
        __half* s = smg + (it % 3) * GEMM_STAGE_ELEMS;
        int k0 = it * 32;
#pragma unroll
        for (int j = 0; j < 2; j++) {
            int c = tid + j * 256;
            int ar = c >> 2, ac = (c & 3) << 3;
            size_t ga = (size_t)(bm * 128 + ar) * K + k0 + ac;
            cp16(s + ar * 40 + ac, Ahg + ga);
            if (use_lo) cp16(s + 5120 + ar * 40 + ac, Alg + ga);
            int br = c >> 4, bc = (c & 15) << 3;
            size_t gb = (size_t)(k0 + br) * Nb + bnn * 128 + bc;
            cp16(s + 10240 + br * 136 + bc, Bg + gb);
        }
        cp_commit();
    };

    issue(0);
    issue(1);
    for (int it = 0; it < NT; it++) {
        if (it + 1 < NT) cp_wait1(); else cp_wait0();
        __syncthreads();
        if (it + 2 < NT) issue(it + 2);
        const __half* s = smg + (it % 3) * GEMM_STAGE_ELEMS;

#pragma unroll
        for (int ks = 0; ks < 2; ks++) {
            const int kk = ks * 16;
            unsigned ah[2][4], al[2][4];
            const int arow = lane & 15, acol = kk + ((lane >> 4) << 3);
#pragma unroll
            for (int mt = 0; mt < 2; mt++) {
                ldm_x4(ah[mt], s2u(s + (wm + mt * 16 + arow) * 40 + acol));
                if (use_lo)
                    ldm_x4(al[mt], s2u(s + 5120 + (wm + mt * 16 + arow) * 40 + acol));
            }
            const int krow = kk + (lane & 7) + ((lane >> 3) & 1) * 8;
#pragma unroll
            for (int ntp = 0; ntp < 4; ntp++) {
                const int ncol = wn + ntp * 16 + ((lane >> 4) << 3);
                unsigned bh[4];
                ldm_x4_t(bh, s2u(s + 10240 + krow * 136 + ncol));
#pragma unroll
                for (int mt = 0; mt < 2; mt++) {
                    mma_f16(d[mt][2 * ntp],     ah[mt], bh);
                    mma_f16(d[mt][2 * ntp + 1], ah[mt], bh + 2);
                    if (use_lo) {
                        mma_f16(d[mt][2 * ntp],     al[mt], bh);
                        mma_f16(d[mt][2 * ntp + 1], al[mt], bh + 2);
                    }
                }
            }
        }
    }

    // epilogue (per segment)
#pragma unroll
    for (int mt = 0; mt < 2; mt++) {
        int r0 = bm * 128 + wm + mt * 16 + g;
#pragma unroll
        for (int nt = 0; nt < 8; nt++) {
            int c = bnn * 128 + wn + nt * 8 + 2 * tg;
            float v0 = d[mt][nt][0] * alpha, v1 = d[mt][nt][1] * alpha;
            float v2 = d[mt][nt][2] * alpha, v3 = d[mt][nt][3] * alpha;
            if (seg == 0) {
                *(unsigned*)(Q_ + (size_t)r0 * NQK + c)       = packh2(v0, v1);
                *(unsigned*)(Q_ + (size_t)(r0 + 8) * NQK + c) = packh2(v2, v3);
            } else if (seg == 1) {
                unsigned h01, l01, h23, l23;
                split2h(v0, v1, h01, l01);
                split2h(v2, v3, h23, l23);
                *(unsigned*)(Kh_ + (size_t)r0 * NQK + c)       = h01;
                *(unsigned*)(Kl_ + (size_t)r0 * NQK + c)       = l01;
                *(unsigned*)(Kh_ + (size_t)(r0 + 8) * NQK + c) = h23;
                *(unsigned*)(Kl_ + (size_t)(r0 + 8) * NQK + c) = l23;
            } else {
                *(unsigned*)(V_ + (size_t)r0 * NV + c)       = packh2(v0, v1);
                *(unsigned*)(V_ + (size_t)(r0 + 8) * NV + c) = packh2(v2, v3);
            }
        }
    }
}

// ---------------------------------------------------------------------------
// Flash attention (fp16) — UNCHANGED from round 8 (bit-identical results).
// Q tile 128 (8 warps x m16), KV tile 64, 3-stage KV, P kept in registers.
// Smem bytes: Qs 18432 | stage x3 44032 = 150528
// ---------------------------------------------------------------------------
#define FLASH_STAGE_BYTES 44032
#define FLASH_SMEM_BYTES  (18432 + 3 * FLASH_STAGE_BYTES)   // 150528

__global__ __launch_bounds__(256, 1)
void flash_tc(const __half* __restrict__ Qg, const __half* __restrict__ Khg,
              const __half* __restrict__ Klg, const __half* __restrict__ V,
              float* __restrict__ out)
{
    extern __shared__ char smc[];
    __half* Qs = (__half*)smc;                     // [128][72]

    const int tid = threadIdx.x, lane = tid & 31, wid = tid >> 5;
    const int g = lane >> 2, tg = lane & 3;
    const int w16 = wid * 16;
    const int b = blockIdx.y >> 3, h = blockIdx.y & 7;
    const int q0 = blockIdx.x * 128;
    const int NT = SEQ / 64;   // 24

#pragma unroll
    for (int r = 0; r < 4; r++) {
        int idx = tid + r * 256;
        int qr = idx >> 3, kc = (idx & 7) << 3;
        *(uint4*)(Qs + qr * 72 + kc) =
            *(const uint4*)(Qg + (size_t)(b * SEQ + q0 + qr) * NQK + h * DK + kc);
    }

    auto issue_kv = [&](int kt) {
        char* st = smc + 18432 + (kt % 3) * FLASH_STAGE_BYTES;
        const int kv0 = kt * 64;
#pragma unroll
        for (int i = 0; i < 2; i++) {
            int idx = tid + i * 256;
            int r = idx >> 3, q = idx & 7;
            size_t go = (size_t)(b * SEQ + kv0 + r) * NQK + h * DK + q * 8;
            cp16(st + r * 144 + q * 16, Khg + go);
            cp16(st + 9216 + r * 144 + q * 16, Klg + go);
        }
#pragma unroll
        for (int i = 0; i < 6; i++) {
            int idx = tid + i * 256;
            int r = idx / 24, cq = idx % 24;
            cp16(st + 18432 + r * 400 + cq * 16,
                 V + (size_t)(b * SEQ + kv0 + r) * NV + h * DV + cq * 8);
        }
        cp_commit();
    };

    issue_kv(0);
    issue_kv(1);
    __syncthreads();

    unsigned qf[4][4];
#pragma unroll
    for (int ks = 0; ks < 4; ks++) {
        const int arow = lane & 15, acol = ks * 16 + ((lane >> 4) << 3);
        ldm_x4(qf[ks], s2u(Qs + (w16 + arow) * 72 + acol));
    }

    float m0 = -1e30f, m1 = -1e30f, l0s = 0.f, l1s = 0.f;
    float o[24][4];
#pragma unroll
    for (int nt = 0; nt < 24; nt++)
#pragma unroll
        for (int i = 0; i < 4; i++) o[nt][i] = 0.f;

    for (int kt = 0; kt < NT; kt++) {
        if (kt + 1 < NT) cp_wait1(); else cp_wait0();
        __syncthreads();
        if (kt + 2 < NT) issue_kv(kt + 2);

        char* st = smc + 18432 + (kt % 3) * FLASH_STAGE_BYTES;
        __half* Kh_s = (__half*)st;
        __half* Kl_s = (__half*)(st + 9216);
        __half* Vs   = (__half*)(st + 18432);

        float s[8][4];
#pragma unroll
        for (int nt = 0; nt < 8; nt++)
#pragma unroll
            for (int i = 0; i < 4; i++) s[nt][i] = 0.f;

#pragma unroll
        for (int ks = 0; ks < 4; ks++) {
            const int kk = ks * 16;
            const int nrow = ((lane >> 4) << 3) + (lane & 7);
            const int kcol = kk + ((lane >> 3) & 1) * 8;
#pragma unroll
            for (int ntp = 0; ntp < 4; ntp++) {
                unsigned kh[4], kl[4];
                ldm_x4(kh, s2u(Kh_s + (ntp * 16 + nrow) * 72 + kcol));
                ldm_x4(kl, s2u(Kl_s + (ntp * 16 + nrow) * 72 + kcol));
                mma_f16(s[2 * ntp],     qf[ks], kh);
                mma_f16(s[2 * ntp],     qf[ks], kl);
                mma_f16(s[2 * ntp + 1], qf[ks], kh + 2);
                mma_f16(s[2 * ntp + 1], qf[ks], kl + 2);
            }
        }

        float mx0 = -1e30f, mx1 = -1e30f;
#pragma unroll
        for (int nt = 0; nt < 8; nt++) {
            mx0 = fmaxf(mx0, fmaxf(s[nt][0], s[nt][1]));
            mx1 = fmaxf(mx1, fmaxf(s[nt][2], s[nt][3]));
        }
        mx0 = fmaxf(mx0, __shfl_xor_sync(0xffffffffu, mx0, 1));
        mx0 = fmaxf(mx0, __shfl_xor_sync(0xffffffffu, mx0, 2));
        mx1 = fmaxf(mx1, __shfl_xor_sync(0xffffffffu, mx1, 1));
        mx1 = fmaxf(mx1, __shfl_xor_sync(0xffffffffu, mx1, 2));

        float nm0 = fmaxf(m0, mx0), nm1 = fmaxf(m1, mx1);
        float a0 = __expf(m0 - nm0), a1 = __expf(m1 - nm1);
        float sum0 = 0.f, sum1 = 0.f;
#pragma unroll
        for (int nt = 0; nt < 8; nt++) {
            s[nt][0] = __expf(s[nt][0] - nm0); sum0 += s[nt][0];
            s[nt][1] = __expf(s[nt][1] - nm0); sum0 += s[nt][1];
            s[nt][2] = __expf(s[nt][2] - nm1); sum1 += s[nt][2];
            s[nt][3] = __expf(s[nt][3] - nm1); sum1 += s[nt][3];
        }
        sum0 += __shfl_xor_sync(0xffffffffu, sum0, 1);
        sum0 += __shfl_xor_sync(0xffffffffu, sum0, 2);
        sum1 += __shfl_xor_sync(0xffffffffu, sum1, 1);
        sum1 += __shfl_xor_sync(0xffffffffu, sum1, 2);
        l0s = l0s * a0 + sum0;  l1s = l1s * a1 + sum1;
        m0 = nm0;  m1 = nm1;

#pragma unroll
        for (int nt = 0; nt < 24; nt++) {
            o[nt][0] *= a0; o[nt][1] *= a0;
            o[nt][2] *= a1; o[nt][3] *= a1;
        }

#pragma unroll
        for (int c = 0; c < 4; c++) {
            unsigned ap[4];
            ap[0] = packh2(s[2 * c][0],     s[2 * c][1]);
            ap[1] = packh2(s[2 * c][2],     s[2 * c][3]);
            ap[2] = packh2(s[2 * c + 1][0], s[2 * c + 1][1]);
            ap[3] = packh2(s[2 * c + 1][2], s[2 * c + 1][3]);
            const int krow = 16 * c + (lane & 7) + ((lane >> 3) & 1) * 8;
#pragma unroll
            for (int ntp = 0; ntp < 12; ntp++) {
                const int ncol = ntp * 16 + ((lane >> 4) << 3);
                unsigned bv[4];
                ldm_x4_t(bv, s2u(Vs + krow * 200 + ncol));
                mma_f16(o[2 * ntp],     ap, bv);
                mma_f16(o[2 * ntp + 1], ap, bv + 2);
            }
        }
    }

    float i0 = 1.f / l0s, i1 = 1.f / l1s;
    int r0 = b * SEQ + q0 + w16 + g, r1 = r0 + 8;
#pragma unroll
    for (int nt = 0; nt < 24; nt++) {
        int c = h * DV + nt * 8 + 2 * tg;
        *(float2*)(out + (size_t)r0 * NV + c) = make_float2(o[nt][0] * i0, o[nt][1] * i0);
        *(float2*)(out + (size_t)r1 * NV + c) = make_float2(o[nt][2] * i1, o[nt][3] * i1);
    }
}

// ---------------------------------------------------------------------------
extern "C" void kernel_launch(void* const* d_in, const int* in_sizes, int n_in,
                              void* d_out, int out_size)
{
    const float* X  = (const float*)d_in[0];
    const float* Wq = (const float*)d_in[1];
    const float* Wk = (const float*)d_in[2];
    const float* Wv = (const float*)d_in[3];
    float* out = (float*)d_out;

    void *xh, *xl, *wq, *wk, *wv, *q, *kh, *kl, *pv;
    cudaGetSymbolAddress(&xh, g_Xh); cudaGetSymbolAddress(&xl, g_Xl);
    cudaGetSymbolAddress(&wq, g_Wq); cudaGetSymbolAddress(&wk, g_Wk);
    cudaGetSymbolAddress(&wv, g_Wv);
    cudaGetSymbolAddress(&q, g_Q);
    cudaGetSymbolAddress(&kh, g_Kh); cudaGetSymbolAddress(&kl, g_Kl);
    cudaGetSymbolAddress(&pv, g_V);

    static bool attr_set = false;
    if (!attr_set) {
        cudaFuncSetAttribute(gemm_fused,
            cudaFuncAttributeMaxDynamicSharedMemorySize, GEMM_SMEM_BYTES);
        cudaFuncSetAttribute(flash_tc,
            cudaFuncAttributeMaxDynamicSharedMemorySize, FLASH_SMEM_BYTES);
        attr_set = true;
    }

    // X -> fp16 hi/lo ; all W -> fp16 single (one launch)
    convert_split_h<<<(MROWS * DMODEL / 4 + 255) / 256, 256>>>(
        (const float4*)X, (uint2*)xh, (uint2*)xl, MROWS * DMODEL / 4);
    convert_w_all<<<(2 * NQK4 + NV4 + 255) / 256, 256>>>(
        (const float4*)Wq, (const float4*)Wk, (const float4*)Wv,
        (uint2*)wq, (uint2*)wk, (uint2*)wv);

    // one fused projection GEMM: Q | K | V
    gemm_fused<<<dim3(20, MROWS / 128), 256, GEMM_SMEM_BYTES>>>(
        (const __half*)xh, (const __half*)xl,
        (const __half*)wq, (const __half*)wk, (const __half*)wv,
        (__half*)q, (__half*)kh, (__half*)kl, (__half*)pv);

    flash_tc<<<dim3(SEQ / 128, BATCH * HEADS), 256, FLASH_SMEM_BYTES>>>(
        (const __half*)q, (const __half*)kh, (const __half*)kl,
        (const __half*)pv, out);
}